// round 2
// baseline (speedup 1.0000x reference)
#include <cuda_runtime.h>
#include <cuda_bf16.h>
#include <cstdint>

// ---------------------------------------------------------------------------
// SemlaLayer: equi + inv attention, B=8, N=256, D_EQUI=64, H=16, D_HEAD=16
// ---------------------------------------------------------------------------
#define Bsz 8
#define Nn  256
#define CEQ 64
#define DIN 256
#define NH  16
#define DH  16
#define L2E 1.4426950408889634f

// Scratch (device globals; no allocation allowed)
__device__ __align__(128) float g_maskL2[Bsz * Nn * Nn];          // mask * log2(e): 0 or -1e30
__device__ __align__(128) float g_proj_e[Bsz * Nn * 3 * CEQ];     // v_equi @ W_coord^T
__device__ __align__(128) float g_proj_i[Bsz * Nn * DIN];         // v_inv  @ W_in^T + b_in
__device__ __align__(128) float g_out_e [Bsz * Nn * 3 * CEQ];     // scaled equi attn output
__device__ __align__(128) float g_out_i [Bsz * Nn * DIN];         // scaled inv attn output

__device__ __forceinline__ float ex2f(float x) {
    float r;
    asm("ex2.approx.ftz.f32 %0, %1;" : "=f"(r) : "f"(x));
    return r;
}

// ---------------------------------------------------------------------------
// Mask: 0 where connected, -1e30 where not; fully-disconnected rows -> all 0.
// One block per (b,q) row. Pre-scaled by log2(e) so attn kernels fold it into
// the ex2 argument with a single FFMA.
// ---------------------------------------------------------------------------
__global__ void mask_kernel(const int* __restrict__ adj, float* __restrict__ maskL2) {
    const int row = blockIdx.x;          // b*Nn + q
    const int k = threadIdx.x;
    const int conn = adj[row * Nn + k] != 0;
    const int any = __syncthreads_or(conn);
    maskL2[row * Nn + k] = conn ? 0.0f : (any ? -1e30f : 0.0f);
}

// ---------------------------------------------------------------------------
// Generic C[M,Nout] = X[M,K] @ W[Nout,K]^T (+ bias). All dims divide 64/16.
// 64x64 block tile, BK=16, 256 threads, 4x4 microtile.
// ---------------------------------------------------------------------------
__global__ void gemm_xwT(const float* __restrict__ X, const float* __restrict__ W,
                         const float* __restrict__ bias, float* __restrict__ C,
                         int M, int Nout, int K) {
    __shared__ __align__(16) float Xs[16][68];
    __shared__ __align__(16) float Ws[16][68];
    const int t = threadIdx.x;
    const int tx = t & 15, ty = t >> 4;
    const int m_base = blockIdx.y * 64, n_base = blockIdx.x * 64;
    const int lm = t >> 2;               // 0..63
    const int lk = (t & 3) * 4;          // 0,4,8,12

    float acc[4][4];
#pragma unroll
    for (int i = 0; i < 4; i++)
#pragma unroll
        for (int j = 0; j < 4; j++) acc[i][j] = 0.0f;

    for (int k0 = 0; k0 < K; k0 += 16) {
        float4 vx = *(const float4*)&X[(size_t)(m_base + lm) * K + k0 + lk];
        float4 vw = *(const float4*)&W[(size_t)(n_base + lm) * K + k0 + lk];
        Xs[lk + 0][lm] = vx.x; Xs[lk + 1][lm] = vx.y; Xs[lk + 2][lm] = vx.z; Xs[lk + 3][lm] = vx.w;
        Ws[lk + 0][lm] = vw.x; Ws[lk + 1][lm] = vw.y; Ws[lk + 2][lm] = vw.z; Ws[lk + 3][lm] = vw.w;
        __syncthreads();
#pragma unroll
        for (int kk = 0; kk < 16; kk++) {
            float a[4], b[4];
#pragma unroll
            for (int i = 0; i < 4; i++) a[i] = Xs[kk][ty * 4 + i];
#pragma unroll
            for (int j = 0; j < 4; j++) b[j] = Ws[kk][tx * 4 + j];
#pragma unroll
            for (int i = 0; i < 4; i++)
#pragma unroll
                for (int j = 0; j < 4; j++) acc[i][j] = fmaf(a[i], b[j], acc[i][j]);
        }
        __syncthreads();
    }
#pragma unroll
    for (int i = 0; i < 4; i++) {
        const int m = m_base + ty * 4 + i;
#pragma unroll
        for (int j = 0; j < 4; j++) {
            const int n = n_base + tx * 4 + j;
            const float bv = bias ? bias[n] : 0.0f;
            C[(size_t)m * Nout + n] = acc[i][j] + bv;
        }
    }
}

// ---------------------------------------------------------------------------
// Equi attention. Grid (qtile=4, cgroup=8, b=8), 256 threads.
// Thread t: q_local = t>>2 (64 q per CTA), kq = t&3 (k strided by 4).
// 8 channels per CTA; per (q,k) loads 32B contiguous em; proj slice in smem.
// Softmax without max-subtraction (inputs ~N(0,1); masked -> exp2 -> 0).
// Fused: out = D * sqrt(SQ) / S^2.
// ---------------------------------------------------------------------------
__global__ void __launch_bounds__(256) equi_attn_kernel(
    const float* __restrict__ em,      // [B,N,N,CEQ]
    const float* __restrict__ maskL2,  // [B,N,N]
    const float* __restrict__ proj_e,  // [B,N,3,CEQ]
    float* __restrict__ out_e)         // [B,N,3,CEQ]
{
    const int qt = blockIdx.x, cg = blockIdx.y, b = blockIdx.z;
    const int t = threadIdx.x;
    const int ql = t >> 2, kq = t & 3;
    const int q = qt * 64 + ql;
    const int c0 = cg * 8;

    __shared__ __align__(16) float proj_s[256][24];  // [k][d*8+j]

    // Preload proj slice for this (b, channel group): 24KB
    for (int i = t; i < 256 * 6; i += 256) {
        const int k = i / 6, r4 = i % 6;
        const int d = r4 >> 1, half = r4 & 1;
        float4 v = *(const float4*)&proj_e[(size_t)((b * Nn + k) * 3 + d) * CEQ + c0 + half * 4];
        *(float4*)&proj_s[k][r4 * 4] = v;
    }
    __syncthreads();

    float S[8], SQ[8], D[24];
#pragma unroll
    for (int j = 0; j < 8; j++) { S[j] = 0.0f; SQ[j] = 0.0f; }
#pragma unroll
    for (int r = 0; r < 24; r++) D[r] = 0.0f;

    const float4* emr = (const float4*)(em + (size_t)(b * Nn + q) * (Nn * CEQ) + c0);
    const float* mrow = maskL2 + (size_t)(b * Nn + q) * Nn;

    for (int k = kq; k < 256; k += 4) {
        const float4 a = emr[k * 16 + 0];
        const float4 bb = emr[k * 16 + 1];
        const float mk = mrow[k];
        float x[8] = {a.x, a.y, a.z, a.w, bb.x, bb.y, bb.z, bb.w};
        float p[8];
#pragma unroll
        for (int j = 0; j < 8; j++) {
            p[j] = ex2f(fmaf(x[j], L2E, mk));
            S[j] += p[j];
            SQ[j] = fmaf(p[j], p[j], SQ[j]);
        }
        const float* pk = proj_s[k];
#pragma unroll
        for (int r = 0; r < 24; r++)
            D[r] = fmaf(p[r & 7], pk[r], D[r]);
    }

    // Merge the 4 k-strided lanes per q (lanes are consecutive in warp)
#pragma unroll
    for (int m = 1; m < 4; m <<= 1) {
#pragma unroll
        for (int j = 0; j < 8; j++) {
            S[j]  += __shfl_xor_sync(0xffffffffu, S[j],  m);
            SQ[j] += __shfl_xor_sync(0xffffffffu, SQ[j], m);
        }
#pragma unroll
        for (int r = 0; r < 24; r++)
            D[r] += __shfl_xor_sync(0xffffffffu, D[r], m);
    }

    if (kq == 0) {
        float* orow = out_e + (size_t)(b * Nn + q) * (3 * CEQ) + c0;
#pragma unroll
        for (int j = 0; j < 8; j++) {
            const float inv = 1.0f / S[j];
            const float sc = sqrtf(SQ[j]) * inv * inv;
#pragma unroll
            for (int d = 0; d < 3; d++)
                orow[d * CEQ + j] = D[d * 8 + j] * sc;
        }
    }
}

// ---------------------------------------------------------------------------
// Inv attention. Grid (qtile=8, hgroup=4, b=8), 256 threads.
// Thread t: q_local = t>>3 (32 q per CTA), kq = t&7. 4 heads x 16 dims per CTA.
// head_feats slice staged in padded smem (stride 68 -> conflict-free LDS.128).
// ---------------------------------------------------------------------------
__global__ void __launch_bounds__(256) inv_attn_kernel(
    const float* __restrict__ im,      // [B,N,N,NH]
    const float* __restrict__ maskL2,  // [B,N,N]
    const float* __restrict__ hf,      // [B,N,DIN]
    float* __restrict__ out_i)         // [B,N,DIN]
{
    extern __shared__ float hf_s[];    // [256][68], uses [64]
    const int qt = blockIdx.x, hg = blockIdx.y, b = blockIdx.z;
    const int t = threadIdx.x;
    const int ql = t >> 3, kq = t & 7;
    const int q = qt * 32 + ql;
    const int h0 = hg * 4;

    // Preload head_feats slice [256k][4h*16e] = 64KB (padded rows)
    for (int i = t; i < 256 * 16; i += 256) {
        const int k = i >> 4, r4 = i & 15;
        float4 v = *(const float4*)&hf[(size_t)(b * Nn + k) * DIN + h0 * 16 + r4 * 4];
        *(float4*)&hf_s[k * 68 + r4 * 4] = v;
    }
    __syncthreads();

    float S[4], SQ[4], A[64];
#pragma unroll
    for (int h = 0; h < 4; h++) { S[h] = 0.0f; SQ[h] = 0.0f; }
#pragma unroll
    for (int r = 0; r < 64; r++) A[r] = 0.0f;

    const float4* imr = (const float4*)(im + (size_t)(b * Nn + q) * (Nn * NH));
    const float* mrow = maskL2 + (size_t)(b * Nn + q) * Nn;

    for (int k = kq; k < 256; k += 8) {
        const float4 v = imr[k * 4 + hg];
        const float mk = mrow[k];
        float p[4];
        p[0] = ex2f(fmaf(v.x, L2E, mk));
        p[1] = ex2f(fmaf(v.y, L2E, mk));
        p[2] = ex2f(fmaf(v.z, L2E, mk));
        p[3] = ex2f(fmaf(v.w, L2E, mk));
#pragma unroll
        for (int h = 0; h < 4; h++) {
            S[h] += p[h];
            SQ[h] = fmaf(p[h], p[h], SQ[h]);
        }
        const float* hk = &hf_s[k * 68];
#pragma unroll
        for (int h = 0; h < 4; h++) {
            const float ph = p[h];
#pragma unroll
            for (int e = 0; e < 16; e++)
                A[h * 16 + e] = fmaf(ph, hk[h * 16 + e], A[h * 16 + e]);
        }
    }

    // Merge the 8 k-strided lanes per q
#pragma unroll
    for (int m = 1; m < 8; m <<= 1) {
#pragma unroll
        for (int h = 0; h < 4; h++) {
            S[h]  += __shfl_xor_sync(0xffffffffu, S[h],  m);
            SQ[h] += __shfl_xor_sync(0xffffffffu, SQ[h], m);
        }
#pragma unroll
        for (int r = 0; r < 64; r++)
            A[r] += __shfl_xor_sync(0xffffffffu, A[r], m);
    }

    if (kq == 0) {
        float* orow = out_i + (size_t)(b * Nn + q) * DIN;
#pragma unroll
        for (int h = 0; h < 4; h++) {
            const float inv = 1.0f / S[h];
            const float sc = sqrtf(SQ[h]) * inv * inv;
#pragma unroll
            for (int e = 0; e < 16; e++)
                orow[(h0 + h) * 16 + e] = A[h * 16 + e] * sc;
        }
    }
}

// ---------------------------------------------------------------------------
// Launch: mask -> input projections -> attentions -> output projections
// ---------------------------------------------------------------------------
extern "C" void kernel_launch(void* const* d_in, const int* in_sizes, int n_in,
                              void* d_out, int out_size) {
    const float* v_equi     = (const float*)d_in[0];   // [8,256,3,64]
    const float* v_inv      = (const float*)d_in[1];   // [8,256,256]
    const float* em         = (const float*)d_in[2];   // [8,256,256,64]
    const float* im         = (const float*)d_in[3];   // [8,256,256,16]
    const int*   adj        = (const int*)  d_in[4];   // [8,256,256]
    const float* W_coord    = (const float*)d_in[5];   // [64,64]
    const float* W_equi_out = (const float*)d_in[6];   // [64,64]
    const float* b_equi_out = (const float*)d_in[7];   // [64]
    const float* W_in       = (const float*)d_in[8];   // [256,256]
    const float* b_in       = (const float*)d_in[9];   // [256]
    const float* W_out      = (const float*)d_in[10];  // [256,256]
    const float* b_out      = (const float*)d_in[11];  // [256]
    float* out = (float*)d_out;

    float *p_mask, *p_proje, *p_proji, *p_oute, *p_outi;
    cudaGetSymbolAddress((void**)&p_mask,  g_maskL2);
    cudaGetSymbolAddress((void**)&p_proje, g_proj_e);
    cudaGetSymbolAddress((void**)&p_proji, g_proj_i);
    cudaGetSymbolAddress((void**)&p_oute,  g_out_e);
    cudaGetSymbolAddress((void**)&p_outi,  g_out_i);

    // 1) mask (with row_any handling), pre-scaled by log2(e)
    mask_kernel<<<Bsz * Nn, Nn>>>(adj, p_mask);

    // 2) input projections
    gemm_xwT<<<dim3(1, (Bsz * Nn * 3) / 64), 256>>>(v_equi, W_coord, nullptr, p_proje,
                                                    Bsz * Nn * 3, CEQ, CEQ);
    gemm_xwT<<<dim3(DIN / 64, (Bsz * Nn) / 64), 256>>>(v_inv, W_in, b_in, p_proji,
                                                       Bsz * Nn, DIN, DIN);

    // 3) attentions
    equi_attn_kernel<<<dim3(4, 8, Bsz), 256>>>(em, p_mask, p_proje, p_oute);

    cudaFuncSetAttribute(inv_attn_kernel, cudaFuncAttributeMaxDynamicSharedMemorySize,
                         256 * 68 * (int)sizeof(float));
    inv_attn_kernel<<<dim3(8, 4, Bsz), 256, 256 * 68 * sizeof(float)>>>(im, p_mask, p_proji, p_outi);

    // 4) output projections straight into d_out (equi first, then inv)
    gemm_xwT<<<dim3(1, (Bsz * Nn * 3) / 64), 256>>>(p_oute, W_equi_out, b_equi_out, out,
                                                    Bsz * Nn * 3, CEQ, CEQ);
    gemm_xwT<<<dim3(DIN / 64, (Bsz * Nn) / 64), 256>>>(p_outi, W_out, b_out,
                                                       out + Bsz * Nn * 3 * CEQ,
                                                       Bsz * Nn, DIN, DIN);
}

// round 3
// speedup vs baseline: 1.1819x; 1.1819x over previous
#include <cuda_runtime.h>
#include <cuda_bf16.h>
#include <cstdint>

// ---------------------------------------------------------------------------
// SemlaLayer: equi + inv attention, B=8, N=256, D_EQUI=64, H=16, D_HEAD=16
// ---------------------------------------------------------------------------
#define Bsz 8
#define Nn  256
#define CEQ 64
#define DIN 256
#define L2E 1.4426950408889634f

// Scratch (device globals; no allocation allowed)
__device__ __align__(128) float g_maskL2[Bsz * Nn * Nn];
__device__ __align__(128) float g_proj_e[Bsz * Nn * 3 * CEQ];
__device__ __align__(128) float g_proj_i[Bsz * Nn * DIN];
__device__ __align__(128) float g_out_e [Bsz * Nn * 3 * CEQ];
__device__ __align__(128) float g_out_i [Bsz * Nn * DIN];

__device__ __forceinline__ float ex2f(float x) {
    float r;
    asm("ex2.approx.ftz.f32 %0, %1;" : "=f"(r) : "f"(x));
    return r;
}

// ---------------------------------------------------------------------------
// Mask: 0 where connected, -1e30 where not; fully-disconnected rows -> all 0.
// ---------------------------------------------------------------------------
__global__ void mask_kernel(const int* __restrict__ adj, float* __restrict__ maskL2) {
    const int row = blockIdx.x;
    const int k = threadIdx.x;
    const int conn = adj[row * Nn + k] != 0;
    const int any = __syncthreads_or(conn);
    maskL2[row * Nn + k] = conn ? 0.0f : (any ? -1e30f : 0.0f);
}

// ---------------------------------------------------------------------------
// C[M,Nout] = X[M,K] @ W[Nout,K]^T (+ bias). 64x64 tile, BK=16, 256 threads.
// ---------------------------------------------------------------------------
__global__ void __launch_bounds__(256) gemm_xwT(
    const float* __restrict__ X, const float* __restrict__ W,
    const float* __restrict__ bias, float* __restrict__ C,
    int M, int Nout, int K) {
    __shared__ __align__(16) float Xs[16][68];
    __shared__ __align__(16) float Ws[16][68];
    const int t = threadIdx.x;
    const int tx = t & 15, ty = t >> 4;
    const int m_base = blockIdx.y * 64, n_base = blockIdx.x * 64;
    const int lm = t >> 2;
    const int lk = (t & 3) * 4;

    float acc[4][4];
#pragma unroll
    for (int i = 0; i < 4; i++)
#pragma unroll
        for (int j = 0; j < 4; j++) acc[i][j] = 0.0f;

    for (int k0 = 0; k0 < K; k0 += 16) {
        float4 vx = *(const float4*)&X[(size_t)(m_base + lm) * K + k0 + lk];
        float4 vw = *(const float4*)&W[(size_t)(n_base + lm) * K + k0 + lk];
        Xs[lk + 0][lm] = vx.x; Xs[lk + 1][lm] = vx.y; Xs[lk + 2][lm] = vx.z; Xs[lk + 3][lm] = vx.w;
        Ws[lk + 0][lm] = vw.x; Ws[lk + 1][lm] = vw.y; Ws[lk + 2][lm] = vw.z; Ws[lk + 3][lm] = vw.w;
        __syncthreads();
#pragma unroll
        for (int kk = 0; kk < 16; kk++) {
            const float4 av = *(const float4*)&Xs[kk][ty * 4];
            const float4 bv = *(const float4*)&Ws[kk][tx * 4];
            const float a[4] = {av.x, av.y, av.z, av.w};
            const float b[4] = {bv.x, bv.y, bv.z, bv.w};
#pragma unroll
            for (int i = 0; i < 4; i++)
#pragma unroll
                for (int j = 0; j < 4; j++) acc[i][j] = fmaf(a[i], b[j], acc[i][j]);
        }
        __syncthreads();
    }
#pragma unroll
    for (int i = 0; i < 4; i++) {
        const int m = m_base + ty * 4 + i;
#pragma unroll
        for (int j = 0; j < 4; j++) {
            const int n = n_base + tx * 4 + j;
            const float bv = bias ? bias[n] : 0.0f;
            C[(size_t)m * Nout + n] = acc[i][j] + bv;
        }
    }
}

// ---------------------------------------------------------------------------
// Equi attention v3. Grid (cg=2, qg=32, b=8), 128 threads (4 warps).
// Warp owns 2 q; lane: c4 = lane&7 (4 channels of 32-ch group), ksub = lane>>3.
// em loads fully coalesced (warp instr covers contiguous 4x128B aligned lines).
// proj k-tiled into smem (12KB), read as conflict-free LDS.128, reused by 2 q.
// ---------------------------------------------------------------------------
#define KT 32
__global__ void __launch_bounds__(128) equi_attn_kernel(
    const float* __restrict__ em,      // [B,N,N,64]
    const float* __restrict__ maskL2,  // [B,N,N]
    const float* __restrict__ proj_e,  // [B,N,3,64]
    float* __restrict__ out_e)         // [B,N,3,64]
{
    const int cg = blockIdx.x, qg = blockIdx.y, b = blockIdx.z;
    const int t = threadIdx.x;
    const int wid = t >> 5, lane = t & 31;
    const int c4 = lane & 7;           // channel chunk (4 floats)
    const int ksub = lane >> 3;        // 0..3
    const int cbase = cg * 32;
    const int q0 = qg * 8 + wid * 2;

    __shared__ __align__(16) float proj_s[KT * 96];  // [k][d*32 + c_local]

    const float* em0 = em + (size_t)(b * Nn + q0) * (Nn * CEQ) + cbase;
    const float* em1 = em0 + Nn * CEQ;
    const float* m0 = maskL2 + (size_t)(b * Nn + q0) * Nn;
    const float* m1 = m0 + Nn;

    float S0[4], SQ0[4], D0[12], S1[4], SQ1[4], D1[12];
#pragma unroll
    for (int j = 0; j < 4; j++) { S0[j] = SQ0[j] = S1[j] = SQ1[j] = 0.0f; }
#pragma unroll
    for (int r = 0; r < 12; r++) { D0[r] = 0.0f; D1[r] = 0.0f; }

#pragma unroll 1
    for (int kb = 0; kb < Nn; kb += KT) {
        __syncthreads();
        // cooperative tile load: KT*3*32 floats = 768 float4
#pragma unroll
        for (int r = 0; r < 6; r++) {
            const int j = t + r * 128;
            const int k = j / 24;
            const int rem = j - k * 24;
            const int d = rem >> 3;
            const int cl = (rem & 7) * 4;
            float4 v = *(const float4*)&proj_e[((size_t)(b * Nn + kb + k) * 3 + d) * CEQ + cbase + cl];
            *(float4*)&proj_s[k * 96 + d * 32 + cl] = v;
        }
        __syncthreads();
#pragma unroll
        for (int it = 0; it < KT / 4; it++) {
            const int kl = it * 4 + ksub;
            const int k = kb + kl;
            const float4 x0 = *(const float4*)&em0[(size_t)k * CEQ + c4 * 4];
            const float4 x1 = *(const float4*)&em1[(size_t)k * CEQ + c4 * 4];
            const float mk0 = m0[k], mk1 = m1[k];
            const float4 pa = *(const float4*)&proj_s[kl * 96 +  0 + c4 * 4];
            const float4 pb = *(const float4*)&proj_s[kl * 96 + 32 + c4 * 4];
            const float4 pc = *(const float4*)&proj_s[kl * 96 + 64 + c4 * 4];
            const float xv0[4] = {x0.x, x0.y, x0.z, x0.w};
            const float xv1[4] = {x1.x, x1.y, x1.z, x1.w};
            const float pv[12] = {pa.x, pa.y, pa.z, pa.w, pb.x, pb.y, pb.z, pb.w,
                                  pc.x, pc.y, pc.z, pc.w};
            float p0[4], p1[4];
#pragma unroll
            for (int j = 0; j < 4; j++) {
                p0[j] = ex2f(fmaf(xv0[j], L2E, mk0));
                p1[j] = ex2f(fmaf(xv1[j], L2E, mk1));
                S0[j] += p0[j];  SQ0[j] = fmaf(p0[j], p0[j], SQ0[j]);
                S1[j] += p1[j];  SQ1[j] = fmaf(p1[j], p1[j], SQ1[j]);
            }
#pragma unroll
            for (int d = 0; d < 3; d++)
#pragma unroll
                for (int j = 0; j < 4; j++) {
                    D0[d * 4 + j] = fmaf(p0[j], pv[d * 4 + j], D0[d * 4 + j]);
                    D1[d * 4 + j] = fmaf(p1[j], pv[d * 4 + j], D1[d * 4 + j]);
                }
        }
    }

    // reduce across the 4 ksub lanes (bits 3,4 of lane)
#pragma unroll
    for (int m = 8; m <= 16; m <<= 1) {
#pragma unroll
        for (int j = 0; j < 4; j++) {
            S0[j]  += __shfl_xor_sync(0xffffffffu, S0[j],  m);
            SQ0[j] += __shfl_xor_sync(0xffffffffu, SQ0[j], m);
            S1[j]  += __shfl_xor_sync(0xffffffffu, S1[j],  m);
            SQ1[j] += __shfl_xor_sync(0xffffffffu, SQ1[j], m);
        }
#pragma unroll
        for (int r = 0; r < 12; r++) {
            D0[r] += __shfl_xor_sync(0xffffffffu, D0[r], m);
            D1[r] += __shfl_xor_sync(0xffffffffu, D1[r], m);
        }
    }

    if (ksub == 0) {
        float sc0[4], sc1[4];
#pragma unroll
        for (int j = 0; j < 4; j++) {
            const float i0 = 1.0f / S0[j];
            const float i1 = 1.0f / S1[j];
            sc0[j] = sqrtf(SQ0[j]) * i0 * i0;
            sc1[j] = sqrtf(SQ1[j]) * i1 * i1;
        }
#pragma unroll
        for (int d = 0; d < 3; d++) {
            float4 o0, o1;
            o0.x = D0[d*4+0]*sc0[0]; o0.y = D0[d*4+1]*sc0[1];
            o0.z = D0[d*4+2]*sc0[2]; o0.w = D0[d*4+3]*sc0[3];
            o1.x = D1[d*4+0]*sc1[0]; o1.y = D1[d*4+1]*sc1[1];
            o1.z = D1[d*4+2]*sc1[2]; o1.w = D1[d*4+3]*sc1[3];
            *(float4*)&out_e[((size_t)(b * Nn + q0) * 3 + d) * CEQ + cbase + c4 * 4] = o0;
            *(float4*)&out_e[((size_t)(b * Nn + q0 + 1) * 3 + d) * CEQ + cbase + c4 * 4] = o1;
        }
    }
}

// ---------------------------------------------------------------------------
// Inv attention v3. Grid (hg=2, qg=32, b=8), 128 threads (4 warps).
// Warp owns 2 q; lane: h = lane&7 (head within 8-head group), ksub = lane>>3.
// Lane accumulates 16 d_head elems per head per q. head_feats tiled in smem
// with padded plane stride 516 -> conflict-free LDS.128 (quarter-warp phases).
// ---------------------------------------------------------------------------
#define KTI 32
__global__ void __launch_bounds__(128) inv_attn_kernel(
    const float* __restrict__ im,      // [B,N,N,16]
    const float* __restrict__ maskL2,  // [B,N,N]
    const float* __restrict__ hf,      // [B,N,256] (head-major h*16+e)
    float* __restrict__ out_i)         // [B,N,256]
{
    const int hg = blockIdx.x, qg = blockIdx.y, b = blockIdx.z;
    const int t = threadIdx.x;
    const int wid = t >> 5, lane = t & 31;
    const int h = lane & 7;
    const int ksub = lane >> 3;
    const int hbase = hg * 8;
    const int q0 = qg * 8 + wid * 2;

    __shared__ __align__(16) float hf_s[8 * 516];  // [h][k*16+e], plane stride 516

    const float* im0 = im + (size_t)(b * Nn + q0) * (Nn * 16) + hbase + h;
    const float* im1 = im0 + Nn * 16;
    const float* m0 = maskL2 + (size_t)(b * Nn + q0) * Nn;
    const float* m1 = m0 + Nn;

    float S0 = 0.0f, SQ0 = 0.0f, S1 = 0.0f, SQ1 = 0.0f;
    float A0[16], A1[16];
#pragma unroll
    for (int e = 0; e < 16; e++) { A0[e] = 0.0f; A1[e] = 0.0f; }

#pragma unroll 1
    for (int kb = 0; kb < Nn; kb += KTI) {
        __syncthreads();
        // tile load: KTI*8h*16e floats = 1024 float4
#pragma unroll
        for (int r = 0; r < 8; r++) {
            const int j = t + r * 128;
            const int k = j >> 5;
            const int rem = j & 31;
            const int hh = rem >> 2;
            const int e4 = (rem & 3) * 4;
            float4 v = *(const float4*)&hf[(size_t)(b * Nn + kb + k) * DIN + (hbase + hh) * 16 + e4];
            *(float4*)&hf_s[hh * 516 + k * 16 + e4] = v;
        }
        __syncthreads();
#pragma unroll
        for (int it = 0; it < KTI / 4; it++) {
            const int kl = it * 4 + ksub;
            const int k = kb + kl;
            const float x0 = im0[(size_t)k * 16];
            const float x1 = im1[(size_t)k * 16];
            const float p0 = ex2f(fmaf(x0, L2E, m0[k]));
            const float p1 = ex2f(fmaf(x1, L2E, m1[k]));
            S0 += p0; SQ0 = fmaf(p0, p0, SQ0);
            S1 += p1; SQ1 = fmaf(p1, p1, SQ1);
            const float* hk = &hf_s[h * 516 + kl * 16];
#pragma unroll
            for (int e4 = 0; e4 < 4; e4++) {
                const float4 v = *(const float4*)&hk[e4 * 4];
                A0[e4*4+0] = fmaf(p0, v.x, A0[e4*4+0]);
                A0[e4*4+1] = fmaf(p0, v.y, A0[e4*4+1]);
                A0[e4*4+2] = fmaf(p0, v.z, A0[e4*4+2]);
                A0[e4*4+3] = fmaf(p0, v.w, A0[e4*4+3]);
                A1[e4*4+0] = fmaf(p1, v.x, A1[e4*4+0]);
                A1[e4*4+1] = fmaf(p1, v.y, A1[e4*4+1]);
                A1[e4*4+2] = fmaf(p1, v.z, A1[e4*4+2]);
                A1[e4*4+3] = fmaf(p1, v.w, A1[e4*4+3]);
            }
        }
    }

    // reduce across the 4 ksub lanes
#pragma unroll
    for (int m = 8; m <= 16; m <<= 1) {
        S0  += __shfl_xor_sync(0xffffffffu, S0,  m);
        SQ0 += __shfl_xor_sync(0xffffffffu, SQ0, m);
        S1  += __shfl_xor_sync(0xffffffffu, S1,  m);
        SQ1 += __shfl_xor_sync(0xffffffffu, SQ1, m);
#pragma unroll
        for (int e = 0; e < 16; e++) {
            A0[e] += __shfl_xor_sync(0xffffffffu, A0[e], m);
            A1[e] += __shfl_xor_sync(0xffffffffu, A1[e], m);
        }
    }

    if (ksub == 0) {
        const float i0 = 1.0f / S0, i1 = 1.0f / S1;
        const float sc0 = sqrtf(SQ0) * i0 * i0;
        const float sc1 = sqrtf(SQ1) * i1 * i1;
        float* o0 = out_i + (size_t)(b * Nn + q0) * DIN + (hbase + h) * 16;
        float* o1 = o0 + DIN;
#pragma unroll
        for (int e4 = 0; e4 < 4; e4++) {
            float4 v0, v1;
            v0.x = A0[e4*4+0]*sc0; v0.y = A0[e4*4+1]*sc0;
            v0.z = A0[e4*4+2]*sc0; v0.w = A0[e4*4+3]*sc0;
            v1.x = A1[e4*4+0]*sc1; v1.y = A1[e4*4+1]*sc1;
            v1.z = A1[e4*4+2]*sc1; v1.w = A1[e4*4+3]*sc1;
            *(float4*)&o0[e4 * 4] = v0;
            *(float4*)&o1[e4 * 4] = v1;
        }
    }
}

// ---------------------------------------------------------------------------
// Launch
// ---------------------------------------------------------------------------
extern "C" void kernel_launch(void* const* d_in, const int* in_sizes, int n_in,
                              void* d_out, int out_size) {
    const float* v_equi     = (const float*)d_in[0];
    const float* v_inv      = (const float*)d_in[1];
    const float* em         = (const float*)d_in[2];
    const float* im         = (const float*)d_in[3];
    const int*   adj        = (const int*)  d_in[4];
    const float* W_coord    = (const float*)d_in[5];
    const float* W_equi_out = (const float*)d_in[6];
    const float* b_equi_out = (const float*)d_in[7];
    const float* W_in       = (const float*)d_in[8];
    const float* b_in       = (const float*)d_in[9];
    const float* W_out      = (const float*)d_in[10];
    const float* b_out      = (const float*)d_in[11];
    float* out = (float*)d_out;

    float *p_mask, *p_proje, *p_proji, *p_oute, *p_outi;
    cudaGetSymbolAddress((void**)&p_mask,  g_maskL2);
    cudaGetSymbolAddress((void**)&p_proje, g_proj_e);
    cudaGetSymbolAddress((void**)&p_proji, g_proj_i);
    cudaGetSymbolAddress((void**)&p_oute,  g_out_e);
    cudaGetSymbolAddress((void**)&p_outi,  g_out_i);

    mask_kernel<<<Bsz * Nn, Nn>>>(adj, p_mask);

    gemm_xwT<<<dim3(1, (Bsz * Nn * 3) / 64), 256>>>(v_equi, W_coord, nullptr, p_proje,
                                                    Bsz * Nn * 3, CEQ, CEQ);
    gemm_xwT<<<dim3(DIN / 64, (Bsz * Nn) / 64), 256>>>(v_inv, W_in, b_in, p_proji,
                                                       Bsz * Nn, DIN, DIN);

    equi_attn_kernel<<<dim3(2, Nn / 8, Bsz), 128>>>(em, p_mask, p_proje, p_oute);
    inv_attn_kernel <<<dim3(2, Nn / 8, Bsz), 128>>>(im, p_mask, p_proji, p_outi);

    gemm_xwT<<<dim3(1, (Bsz * Nn * 3) / 64), 256>>>(p_oute, W_equi_out, b_equi_out, out,
                                                    Bsz * Nn * 3, CEQ, CEQ);
    gemm_xwT<<<dim3(DIN / 64, (Bsz * Nn) / 64), 256>>>(p_outi, W_out, b_out,
                                                       out + Bsz * Nn * 3 * CEQ,
                                                       Bsz * Nn, DIN, DIN);
}

// round 7
// speedup vs baseline: 1.3928x; 1.1784x over previous
#include <cuda_runtime.h>
#include <cuda_bf16.h>
#include <cstdint>

// ---------------------------------------------------------------------------
// SemlaLayer: equi + inv attention, B=8, N=256, D_EQUI=64, H=16, D_HEAD=16
// ---------------------------------------------------------------------------
#define Bsz 8
#define Nn  256
#define CEQ 64
#define DIN 256
#define L2E 1.4426950408889634f
#define KT  32

// Scratch (device globals; no allocation allowed)
__device__ __align__(128) float g_maskL2[Bsz * Nn * Nn];
__device__ __align__(128) float g_proj_e[Bsz * Nn * 3 * CEQ];
__device__ __align__(128) float g_proj_i[Bsz * Nn * DIN];
__device__ __align__(128) float g_out_e [Bsz * Nn * 3 * CEQ];
__device__ __align__(128) float g_out_i [Bsz * Nn * DIN];

__device__ __forceinline__ float ex2f(float x) {
    float r;
    asm("ex2.approx.ftz.f32 %0, %1;" : "=f"(r) : "f"(x));
    return r;
}

__device__ __forceinline__ void cp16(float* dst_smem, const float* src) {
    uint32_t d = (uint32_t)__cvta_generic_to_shared(dst_smem);
    asm volatile("cp.async.cg.shared.global [%0], [%1], 16;" :: "r"(d), "l"(src) : "memory");
}
__device__ __forceinline__ void cp_commit() {
    asm volatile("cp.async.commit_group;" ::: "memory");
}
template <int N> __device__ __forceinline__ void cp_wait() {
    asm volatile("cp.async.wait_group %0;" :: "n"(N) : "memory");
}

// ---------------------------------------------------------------------------
// GEMM tile device function: C[m_base:+64, n_base:+64] = X @ W^T (+bias)
// 256 threads, BK=16, 4x4 microtile. sm: 2*16*68 floats.
// ---------------------------------------------------------------------------
__device__ __forceinline__ void gemm_tile(
    const float* __restrict__ X, const float* __restrict__ W,
    const float* __restrict__ bias, float* __restrict__ C,
    int Nout, int K, int m_base, int n_base, float* sm)
{
    float (*Xs)[68] = (float(*)[68])sm;
    float (*Ws)[68] = (float(*)[68])(sm + 16 * 68);
    const int t = threadIdx.x;
    const int tx = t & 15, ty = t >> 4;
    const int lm = t >> 2;
    const int lk = (t & 3) * 4;

    float acc[4][4];
#pragma unroll
    for (int i = 0; i < 4; i++)
#pragma unroll
        for (int j = 0; j < 4; j++) acc[i][j] = 0.0f;

    for (int k0 = 0; k0 < K; k0 += 16) {
        float4 vx = *(const float4*)&X[(size_t)(m_base + lm) * K + k0 + lk];
        float4 vw = *(const float4*)&W[(size_t)(n_base + lm) * K + k0 + lk];
        Xs[lk + 0][lm] = vx.x; Xs[lk + 1][lm] = vx.y; Xs[lk + 2][lm] = vx.z; Xs[lk + 3][lm] = vx.w;
        Ws[lk + 0][lm] = vw.x; Ws[lk + 1][lm] = vw.y; Ws[lk + 2][lm] = vw.z; Ws[lk + 3][lm] = vw.w;
        __syncthreads();
#pragma unroll
        for (int kk = 0; kk < 16; kk++) {
            const float4 av = *(const float4*)&Xs[kk][ty * 4];
            const float4 bv = *(const float4*)&Ws[kk][tx * 4];
            const float a[4] = {av.x, av.y, av.z, av.w};
            const float b[4] = {bv.x, bv.y, bv.z, bv.w};
#pragma unroll
            for (int i = 0; i < 4; i++)
#pragma unroll
                for (int j = 0; j < 4; j++) acc[i][j] = fmaf(a[i], b[j], acc[i][j]);
        }
        __syncthreads();
    }
#pragma unroll
    for (int i = 0; i < 4; i++) {
        const int m = m_base + ty * 4 + i;
#pragma unroll
        for (int j = 0; j < 4; j++) {
            const int n = n_base + tx * 4 + j;
            const float bv = bias ? bias[n] : 0.0f;
            C[(size_t)m * Nout + n] = acc[i][j] + bv;
        }
    }
}

// ---------------------------------------------------------------------------
// Prep kernel: [0,96) equi input GEMM, [96,224) inv input GEMM, [224,480) mask
// ---------------------------------------------------------------------------
__global__ void __launch_bounds__(256) prep_kernel(
    const float* __restrict__ v_equi, const float* __restrict__ v_inv,
    const int* __restrict__ adj,
    const float* __restrict__ W_coord,
    const float* __restrict__ W_in, const float* __restrict__ b_in)
{
    __shared__ __align__(16) float sm[2 * 16 * 68];
    const int bx = blockIdx.x;
    if (bx < 96) {
        gemm_tile(v_equi, W_coord, nullptr, g_proj_e, CEQ, CEQ, bx * 64, 0, sm);
    } else if (bx < 224) {
        const int id = bx - 96;                 // 32 m-tiles x 4 n-tiles
        gemm_tile(v_inv, W_in, b_in, g_proj_i, DIN, DIN, (id >> 2) * 64, (id & 3) * 64, sm);
    } else {
        const int rb = bx - 224;                // 256 CTAs x 8 rows
#pragma unroll
        for (int r = 0; r < 8; r++) {
            const int row = rb * 8 + r;
            const int conn = adj[row * Nn + threadIdx.x] != 0;
            const int any = __syncthreads_or(conn);
            g_maskL2[row * Nn + threadIdx.x] = conn ? 0.0f : (any ? -1e30f : 0.0f);
        }
    }
}

// ---------------------------------------------------------------------------
// Fused attention kernel. 128 threads (4 warps), each warp owns one q.
// blockIdx.x < 1024: equi (cg,qg,b);  >= 1024: inv (hg,qg,b).
// cp.async double-buffered k-tiles, mask rows staged in smem.
// ---------------------------------------------------------------------------
union __align__(16) AttnSm {
    struct { float proj[2][KT * 96]; float mask[4 * 256]; } e;   // 28.0 KB
    struct { float hf[2][8 * 516];   float mask[4 * 256]; } i;   // 36.3 KB
};

__global__ void __launch_bounds__(128) attn_kernel(
    const float* __restrict__ em,      // [B,N,N,64]
    const float* __restrict__ im)      // [B,N,N,16]
{
    __shared__ AttnSm sm;
    const int bx = blockIdx.x;
    const int t = threadIdx.x;
    const int wid = t >> 5, lane = t & 31;
    const int ksub = lane >> 3;

    if (bx < 1024) {
        // ================= EQUI =================
        const int cg = bx & 1, qg = (bx >> 1) & 63, b = bx >> 7;
        const int c4 = lane & 7;
        const int cbase = cg * 32;
        const int q = qg * 4 + wid;

        // mask rows for 4 q
#pragma unroll
        for (int r = 0; r < 8; r++) {
            const int i = t + r * 128;
            sm.e.mask[i] = g_maskL2[(size_t)(b * Nn + qg * 4 + (i >> 8)) * Nn + (i & 255)];
        }
        // prefetch tile 0
#pragma unroll
        for (int r = 0; r < 6; r++) {
            const int j = t + r * 128;
            const int k = j / 24, rem = j - k * 24;
            const int d = rem >> 3, cl = (rem & 7) * 4;
            cp16(&sm.e.proj[0][k * 96 + d * 32 + cl],
                 &g_proj_e[((size_t)(b * Nn + k) * 3 + d) * CEQ + cbase + cl]);
        }
        cp_commit();

        float S[4], SQ[4], D[12];
#pragma unroll
        for (int j = 0; j < 4; j++) { S[j] = 0.0f; SQ[j] = 0.0f; }
#pragma unroll
        for (int r = 0; r < 12; r++) D[r] = 0.0f;

        const float* emq = em + (size_t)(b * Nn + q) * (Nn * CEQ) + cbase;
        const float* mq = sm.e.mask + wid * 256;

        int buf = 0;
#pragma unroll 1
        for (int ti = 0; ti < Nn / KT; ti++) {
            if (ti + 1 < Nn / KT) {
                const int kb2 = (ti + 1) * KT;
#pragma unroll
                for (int r = 0; r < 6; r++) {
                    const int j = t + r * 128;
                    const int k = j / 24, rem = j - k * 24;
                    const int d = rem >> 3, cl = (rem & 7) * 4;
                    cp16(&sm.e.proj[buf ^ 1][k * 96 + d * 32 + cl],
                         &g_proj_e[((size_t)(b * Nn + kb2 + k) * 3 + d) * CEQ + cbase + cl]);
                }
                cp_commit();
                cp_wait<1>();
            } else {
                cp_wait<0>();
            }
            __syncthreads();
            const float* ps = sm.e.proj[buf];
            const int kb = ti * KT;
#pragma unroll
            for (int it = 0; it < KT / 4; it++) {
                const int kl = it * 4 + ksub;
                const int k = kb + kl;
                const float4 x = *(const float4*)&emq[(size_t)k * CEQ + c4 * 4];
                const float mk = mq[k];
                const float4 pa = *(const float4*)&ps[kl * 96 +  0 + c4 * 4];
                const float4 pb = *(const float4*)&ps[kl * 96 + 32 + c4 * 4];
                const float4 pc = *(const float4*)&ps[kl * 96 + 64 + c4 * 4];
                const float xv[4] = {x.x, x.y, x.z, x.w};
                const float pv[12] = {pa.x, pa.y, pa.z, pa.w, pb.x, pb.y, pb.z, pb.w,
                                      pc.x, pc.y, pc.z, pc.w};
                float p[4];
#pragma unroll
                for (int j = 0; j < 4; j++) {
                    p[j] = ex2f(fmaf(xv[j], L2E, mk));
                    S[j] += p[j];
                    SQ[j] = fmaf(p[j], p[j], SQ[j]);
                }
#pragma unroll
                for (int d = 0; d < 3; d++)
#pragma unroll
                    for (int j = 0; j < 4; j++)
                        D[d * 4 + j] = fmaf(p[j], pv[d * 4 + j], D[d * 4 + j]);
            }
            __syncthreads();
            buf ^= 1;
        }

#pragma unroll
        for (int m = 8; m <= 16; m <<= 1) {
#pragma unroll
            for (int j = 0; j < 4; j++) {
                S[j]  += __shfl_xor_sync(0xffffffffu, S[j],  m);
                SQ[j] += __shfl_xor_sync(0xffffffffu, SQ[j], m);
            }
#pragma unroll
            for (int r = 0; r < 12; r++)
                D[r] += __shfl_xor_sync(0xffffffffu, D[r], m);
        }

        if (ksub == 0) {
            float sc[4];
#pragma unroll
            for (int j = 0; j < 4; j++) {
                const float iv = 1.0f / S[j];
                sc[j] = sqrtf(SQ[j]) * iv * iv;
            }
#pragma unroll
            for (int d = 0; d < 3; d++) {
                float4 o;
                o.x = D[d*4+0]*sc[0]; o.y = D[d*4+1]*sc[1];
                o.z = D[d*4+2]*sc[2]; o.w = D[d*4+3]*sc[3];
                *(float4*)&g_out_e[((size_t)(b * Nn + q) * 3 + d) * CEQ + cbase + c4 * 4] = o;
            }
        }
    } else {
        // ================= INV =================
        const int id = bx - 1024;
        const int hg = id & 1, qg = (id >> 1) & 63, b = id >> 7;
        const int h = lane & 7;
        const int hbase = hg * 8;
        const int q = qg * 4 + wid;

#pragma unroll
        for (int r = 0; r < 8; r++) {
            const int i = t + r * 128;
            sm.i.mask[i] = g_maskL2[(size_t)(b * Nn + qg * 4 + (i >> 8)) * Nn + (i & 255)];
        }
#pragma unroll
        for (int r = 0; r < 8; r++) {
            const int j = t + r * 128;
            const int k = j >> 5, rem = j & 31;
            const int hh = rem >> 2, e4 = (rem & 3) * 4;
            cp16(&sm.i.hf[0][hh * 516 + k * 16 + e4],
                 &g_proj_i[(size_t)(b * Nn + k) * DIN + (hbase + hh) * 16 + e4]);
        }
        cp_commit();

        float S = 0.0f, SQ = 0.0f, A[16];
#pragma unroll
        for (int e = 0; e < 16; e++) A[e] = 0.0f;

        const float* imq = im + (size_t)(b * Nn + q) * (Nn * 16) + hbase + h;
        const float* mq = sm.i.mask + wid * 256;

        int buf = 0;
#pragma unroll 1
        for (int ti = 0; ti < Nn / KT; ti++) {
            if (ti + 1 < Nn / KT) {
                const int kb2 = (ti + 1) * KT;
#pragma unroll
                for (int r = 0; r < 8; r++) {
                    const int j = t + r * 128;
                    const int k = j >> 5, rem = j & 31;
                    const int hh = rem >> 2, e4 = (rem & 3) * 4;
                    cp16(&sm.i.hf[buf ^ 1][hh * 516 + k * 16 + e4],
                         &g_proj_i[(size_t)(b * Nn + kb2 + k) * DIN + (hbase + hh) * 16 + e4]);
                }
                cp_commit();
                cp_wait<1>();
            } else {
                cp_wait<0>();
            }
            __syncthreads();
            const float* hs = sm.i.hf[buf];
            const int kb = ti * KT;
#pragma unroll
            for (int it = 0; it < KT / 4; it++) {
                const int kl = it * 4 + ksub;
                const int k = kb + kl;
                const float x = imq[(size_t)k * 16];
                const float p = ex2f(fmaf(x, L2E, mq[k]));
                S += p;
                SQ = fmaf(p, p, SQ);
                const float* hk = hs + h * 516 + kl * 16;
#pragma unroll
                for (int e4 = 0; e4 < 4; e4++) {
                    const float4 v = *(const float4*)&hk[e4 * 4];
                    A[e4*4+0] = fmaf(p, v.x, A[e4*4+0]);
                    A[e4*4+1] = fmaf(p, v.y, A[e4*4+1]);
                    A[e4*4+2] = fmaf(p, v.z, A[e4*4+2]);
                    A[e4*4+3] = fmaf(p, v.w, A[e4*4+3]);
                }
            }
            __syncthreads();
            buf ^= 1;
        }

#pragma unroll
        for (int m = 8; m <= 16; m <<= 1) {
            S  += __shfl_xor_sync(0xffffffffu, S,  m);
            SQ += __shfl_xor_sync(0xffffffffu, SQ, m);
#pragma unroll
            for (int e = 0; e < 16; e++)
                A[e] += __shfl_xor_sync(0xffffffffu, A[e], m);
        }

        if (ksub == 0) {
            const float iv = 1.0f / S;
            const float sc = sqrtf(SQ) * iv * iv;
            float* o = g_out_i + (size_t)(b * Nn + q) * DIN + (hbase + h) * 16;
#pragma unroll
            for (int e4 = 0; e4 < 4; e4++) {
                float4 v;
                v.x = A[e4*4+0]*sc; v.y = A[e4*4+1]*sc;
                v.z = A[e4*4+2]*sc; v.w = A[e4*4+3]*sc;
                *(float4*)&o[e4 * 4] = v;
            }
        }
    }
}

// ---------------------------------------------------------------------------
// Output kernel: [0,96) equi out GEMM, [96,224) inv out GEMM
// ---------------------------------------------------------------------------
__global__ void __launch_bounds__(256) out_kernel(
    const float* __restrict__ W_equi_out, const float* __restrict__ b_equi_out,
    const float* __restrict__ W_out, const float* __restrict__ b_out,
    float* __restrict__ out)
{
    __shared__ __align__(16) float sm[2 * 16 * 68];
    const int bx = blockIdx.x;
    if (bx < 96) {
        gemm_tile(g_out_e, W_equi_out, b_equi_out, out, CEQ, CEQ, bx * 64, 0, sm);
    } else {
        const int id = bx - 96;
        gemm_tile(g_out_i, W_out, b_out, out + (size_t)Bsz * Nn * 3 * CEQ,
                  DIN, DIN, (id >> 2) * 64, (id & 3) * 64, sm);
    }
}

// ---------------------------------------------------------------------------
// Launch: 3 kernels
// ---------------------------------------------------------------------------
extern "C" void kernel_launch(void* const* d_in, const int* in_sizes, int n_in,
                              void* d_out, int out_size) {
    const float* v_equi     = (const float*)d_in[0];
    const float* v_inv      = (const float*)d_in[1];
    const float* em         = (const float*)d_in[2];
    const float* im         = (const float*)d_in[3];
    const int*   adj        = (const int*)  d_in[4];
    const float* W_coord    = (const float*)d_in[5];
    const float* W_equi_out = (const float*)d_in[6];
    const float* b_equi_out = (const float*)d_in[7];
    const float* W_in       = (const float*)d_in[8];
    const float* b_in       = (const float*)d_in[9];
    const float* W_out      = (const float*)d_in[10];
    const float* b_out      = (const float*)d_in[11];
    float* out = (float*)d_out;

    prep_kernel<<<480, 256>>>(v_equi, v_inv, adj, W_coord, W_in, b_in);
    attn_kernel<<<2048, 128>>>(em, im);
    out_kernel<<<224, 256>>>(W_equi_out, b_equi_out, W_out, b_out, out);
}

// round 8
// speedup vs baseline: 1.4485x; 1.0400x over previous
#include <cuda_runtime.h>
#include <cuda_bf16.h>
#include <cstdint>

// ---------------------------------------------------------------------------
// SemlaLayer: equi + inv attention, B=8, N=256, D_EQUI=64, H=16, D_HEAD=16
// ---------------------------------------------------------------------------
#define Bsz 8
#define Nn  256
#define CEQ 64
#define DIN 256
#define L2E 1.4426950408889634f
#define KT  32
#define KTI 16

typedef unsigned long long u64;

// Scratch (device globals; no allocation allowed)
__device__ __align__(128) float g_proj_e[Bsz * Nn * 3 * CEQ];
__device__ __align__(128) float g_proj_i[Bsz * Nn * DIN];
__device__ __align__(128) float g_out_e [Bsz * Nn * 3 * CEQ];
__device__ __align__(128) float g_out_i [Bsz * Nn * DIN];

__device__ __forceinline__ float ex2f(float x) {
    float r;
    asm("ex2.approx.ftz.f32 %0, %1;" : "=f"(r) : "f"(x));
    return r;
}
__device__ __forceinline__ u64 pack2(float lo, float hi) {
    u64 r;
    asm("mov.b64 %0, {%1, %2};" : "=l"(r) : "f"(lo), "f"(hi));
    return r;
}
__device__ __forceinline__ float2 unpack2(u64 v) {
    float2 f;
    asm("mov.b64 {%0, %1}, %2;" : "=f"(f.x), "=f"(f.y) : "l"(v));
    return f;
}
__device__ __forceinline__ void fma2(u64& d, u64 a, u64 b) {
    asm("fma.rn.f32x2 %0, %1, %2, %3;" : "=l"(d) : "l"(a), "l"(b), "l"(d));
}
__device__ __forceinline__ void add2(u64& d, u64 a) {
    asm("add.rn.f32x2 %0, %1, %2;" : "=l"(d) : "l"(a), "l"(d));
}

__device__ __forceinline__ void cp16(float* dst_smem, const float* src) {
    uint32_t d = (uint32_t)__cvta_generic_to_shared(dst_smem);
    asm volatile("cp.async.cg.shared.global [%0], [%1], 16;" :: "r"(d), "l"(src) : "memory");
}
__device__ __forceinline__ void cp_commit() {
    asm volatile("cp.async.commit_group;" ::: "memory");
}
template <int N> __device__ __forceinline__ void cp_wait() {
    asm volatile("cp.async.wait_group %0;" :: "n"(N) : "memory");
}

// ---------------------------------------------------------------------------
// Pipelined GEMM tile: C[m_base:+64, n_base:+64] = X @ W^T (+bias)
// 256 threads, BK=16, double-buffered smem (1 sync per step).
// sm: 4*16*68 floats (17.4 KB).
// ---------------------------------------------------------------------------
__device__ __forceinline__ void gemm_tile(
    const float* __restrict__ X, const float* __restrict__ W,
    const float* __restrict__ bias, float* __restrict__ C,
    int Nout, int K, int m_base, int n_base, float* sm)
{
    const int t = threadIdx.x;
    const int tx = t & 15, ty = t >> 4;
    const int lm = t >> 2;
    const int lk = (t & 3) * 4;

    float acc[4][4];
#pragma unroll
    for (int i = 0; i < 4; i++)
#pragma unroll
        for (int j = 0; j < 4; j++) acc[i][j] = 0.0f;

    // initial tile -> buf 0
    {
        float4 vx = *(const float4*)&X[(size_t)(m_base + lm) * K + lk];
        float4 vw = *(const float4*)&W[(size_t)(n_base + lm) * K + lk];
        float* Xs = sm;
        float* Ws = sm + 1088;
        Xs[(lk + 0) * 68 + lm] = vx.x; Xs[(lk + 1) * 68 + lm] = vx.y;
        Xs[(lk + 2) * 68 + lm] = vx.z; Xs[(lk + 3) * 68 + lm] = vx.w;
        Ws[(lk + 0) * 68 + lm] = vw.x; Ws[(lk + 1) * 68 + lm] = vw.y;
        Ws[(lk + 2) * 68 + lm] = vw.z; Ws[(lk + 3) * 68 + lm] = vw.w;
    }
    __syncthreads();

    const int nsteps = K / 16;
    for (int s = 0; s < nsteps; s++) {
        float4 nx, nw;
        const bool more = (s + 1 < nsteps);
        if (more) {
            nx = *(const float4*)&X[(size_t)(m_base + lm) * K + (s + 1) * 16 + lk];
            nw = *(const float4*)&W[(size_t)(n_base + lm) * K + (s + 1) * 16 + lk];
        }
        const float* Xs = sm + (s & 1) * 2176;
        const float* Ws = Xs + 1088;
#pragma unroll
        for (int kk = 0; kk < 16; kk++) {
            const float4 av = *(const float4*)&Xs[kk * 68 + ty * 4];
            const float4 bv = *(const float4*)&Ws[kk * 68 + tx * 4];
            const float a[4] = {av.x, av.y, av.z, av.w};
            const float b[4] = {bv.x, bv.y, bv.z, bv.w};
#pragma unroll
            for (int i = 0; i < 4; i++)
#pragma unroll
                for (int j = 0; j < 4; j++) acc[i][j] = fmaf(a[i], b[j], acc[i][j]);
        }
        if (more) {
            float* Xd = sm + ((s + 1) & 1) * 2176;
            float* Wd = Xd + 1088;
            Xd[(lk + 0) * 68 + lm] = nx.x; Xd[(lk + 1) * 68 + lm] = nx.y;
            Xd[(lk + 2) * 68 + lm] = nx.z; Xd[(lk + 3) * 68 + lm] = nx.w;
            Wd[(lk + 0) * 68 + lm] = nw.x; Wd[(lk + 1) * 68 + lm] = nw.y;
            Wd[(lk + 2) * 68 + lm] = nw.z; Wd[(lk + 3) * 68 + lm] = nw.w;
        }
        __syncthreads();
    }
#pragma unroll
    for (int i = 0; i < 4; i++) {
        const int m = m_base + ty * 4 + i;
#pragma unroll
        for (int j = 0; j < 4; j++) {
            const int n = n_base + tx * 4 + j;
            const float bv = bias ? bias[n] : 0.0f;
            C[(size_t)m * Nout + n] = acc[i][j] + bv;
        }
    }
}

// ---------------------------------------------------------------------------
// Prep kernel: [0,96) equi input GEMM, [96,224) inv input GEMM
// ---------------------------------------------------------------------------
__global__ void __launch_bounds__(256) prep_kernel(
    const float* __restrict__ v_equi, const float* __restrict__ v_inv,
    const float* __restrict__ W_coord,
    const float* __restrict__ W_in, const float* __restrict__ b_in)
{
    __shared__ __align__(16) float sm[4 * 16 * 68];
    const int bx = blockIdx.x;
    if (bx < 96) {
        gemm_tile(v_equi, W_coord, nullptr, g_proj_e, CEQ, CEQ, bx * 64, 0, sm);
    } else {
        const int id = bx - 96;                 // 32 m-tiles x 4 n-tiles
        gemm_tile(v_inv, W_in, b_in, g_proj_i, DIN, DIN, (id >> 2) * 64, (id & 3) * 64, sm);
    }
}

// ---------------------------------------------------------------------------
// Fused attention kernel. 128 threads (4 warps), each warp owns one q.
// blockIdx.x < 1024: equi;  >= 1024: inv.
// Mask computed in-kernel from adj (ballot row_any). cp.async double-buffered
// k-tiles. All accumulator math packed f32x2.
// ---------------------------------------------------------------------------
union __align__(16) AttnSm {
    struct { float proj[2][KT * 96];  float mask[4 * 256]; } e;   // 28 KB
    struct { float hf[2][8 * 260];    float mask[4 * 256]; } i;   // 20.6 KB
};

__global__ void __launch_bounds__(128) attn_kernel(
    const float* __restrict__ em,      // [B,N,N,64]
    const float* __restrict__ im,      // [B,N,N,16]
    const int*   __restrict__ adj)     // [B,N,N]
{
    __shared__ AttnSm sm;
    const int bx = blockIdx.x;
    const int t = threadIdx.x;
    const int wid = t >> 5, lane = t & 31;
    const int ksub = lane >> 3;

    if (bx < 1024) {
        // ================= EQUI =================
        const int cg = bx & 1, qg = (bx >> 1) & 63, b = bx >> 7;
        const int c4 = lane & 7;
        const int cbase = cg * 32;
        const int q = qg * 4 + wid;

        // mask from adj: warp owns its q-row
        {
            const int* arow = adj + (size_t)(b * Nn + q) * Nn;
            const int4 a0 = *(const int4*)&arow[lane * 8];
            const int4 a1 = *(const int4*)&arow[lane * 8 + 4];
            const bool c0 = a0.x != 0, c1 = a0.y != 0, c2 = a0.z != 0, c3 = a0.w != 0;
            const bool c5 = a1.x != 0, c6 = a1.y != 0, c7 = a1.z != 0, c8 = a1.w != 0;
            const unsigned any = __ballot_sync(0xffffffffu,
                c0 | c1 | c2 | c3 | c5 | c6 | c7 | c8);
            const float neg = any ? -1e30f : 0.0f;
            float4 m0, m1;
            m0.x = c0 ? 0.0f : neg; m0.y = c1 ? 0.0f : neg;
            m0.z = c2 ? 0.0f : neg; m0.w = c3 ? 0.0f : neg;
            m1.x = c5 ? 0.0f : neg; m1.y = c6 ? 0.0f : neg;
            m1.z = c7 ? 0.0f : neg; m1.w = c8 ? 0.0f : neg;
            *(float4*)&sm.e.mask[wid * 256 + lane * 8] = m0;
            *(float4*)&sm.e.mask[wid * 256 + lane * 8 + 4] = m1;
        }
        // prefetch tile 0
#pragma unroll
        for (int r = 0; r < 6; r++) {
            const int j = t + r * 128;
            const int k = j / 24, rem = j - k * 24;
            const int d = rem >> 3, cl = (rem & 7) * 4;
            cp16(&sm.e.proj[0][k * 96 + d * 32 + cl],
                 &g_proj_e[((size_t)(b * Nn + k) * 3 + d) * CEQ + cbase + cl]);
        }
        cp_commit();

        u64 S2[2], SQ2[2], D2[6];
#pragma unroll
        for (int j = 0; j < 2; j++) { S2[j] = 0ull; SQ2[j] = 0ull; }
#pragma unroll
        for (int r = 0; r < 6; r++) D2[r] = 0ull;

        const float* emq = em + (size_t)(b * Nn + q) * (Nn * CEQ) + cbase;
        const float* mq = sm.e.mask + wid * 256;

        int buf = 0;
#pragma unroll 1
        for (int ti = 0; ti < Nn / KT; ti++) {
            if (ti + 1 < Nn / KT) {
                const int kb2 = (ti + 1) * KT;
#pragma unroll
                for (int r = 0; r < 6; r++) {
                    const int j = t + r * 128;
                    const int k = j / 24, rem = j - k * 24;
                    const int d = rem >> 3, cl = (rem & 7) * 4;
                    cp16(&sm.e.proj[buf ^ 1][k * 96 + d * 32 + cl],
                         &g_proj_e[((size_t)(b * Nn + kb2 + k) * 3 + d) * CEQ + cbase + cl]);
                }
                cp_commit();
                cp_wait<1>();
            } else {
                cp_wait<0>();
            }
            __syncthreads();
            const float* ps = sm.e.proj[buf];
            const int kb = ti * KT;
#pragma unroll
            for (int it = 0; it < KT / 4; it++) {
                const int kl = it * 4 + ksub;
                const int k = kb + kl;
                const float4 x = *(const float4*)&emq[(size_t)k * CEQ + c4 * 4];
                const float mk = mq[k];
                const float p0 = ex2f(fmaf(x.x, L2E, mk));
                const float p1 = ex2f(fmaf(x.y, L2E, mk));
                const float p2 = ex2f(fmaf(x.z, L2E, mk));
                const float p3 = ex2f(fmaf(x.w, L2E, mk));
                const u64 pA = pack2(p0, p1), pB = pack2(p2, p3);
                add2(S2[0], pA);        add2(S2[1], pB);
                fma2(SQ2[0], pA, pA);   fma2(SQ2[1], pB, pB);
                const ulonglong2 va = *(const ulonglong2*)&ps[kl * 96 +  0 + c4 * 4];
                const ulonglong2 vb = *(const ulonglong2*)&ps[kl * 96 + 32 + c4 * 4];
                const ulonglong2 vc = *(const ulonglong2*)&ps[kl * 96 + 64 + c4 * 4];
                fma2(D2[0], pA, va.x);  fma2(D2[1], pB, va.y);
                fma2(D2[2], pA, vb.x);  fma2(D2[3], pB, vb.y);
                fma2(D2[4], pA, vc.x);  fma2(D2[5], pB, vc.y);
            }
            __syncthreads();
            buf ^= 1;
        }

#pragma unroll
        for (int m = 8; m <= 16; m <<= 1) {
#pragma unroll
            for (int j = 0; j < 2; j++) {
                const u64 s = __shfl_xor_sync(0xffffffffu, S2[j], m);  add2(S2[j], s);
                const u64 sq = __shfl_xor_sync(0xffffffffu, SQ2[j], m); add2(SQ2[j], sq);
            }
#pragma unroll
            for (int r = 0; r < 6; r++) {
                const u64 d = __shfl_xor_sync(0xffffffffu, D2[r], m);  add2(D2[r], d);
            }
        }

        if (ksub == 0) {
            const float2 sA = unpack2(S2[0]), sB = unpack2(S2[1]);
            const float2 qA = unpack2(SQ2[0]), qB = unpack2(SQ2[1]);
            const float Sv[4] = {sA.x, sA.y, sB.x, sB.y};
            const float Qv[4] = {qA.x, qA.y, qB.x, qB.y};
            float sc[4];
#pragma unroll
            for (int j = 0; j < 4; j++) {
                const float iv = 1.0f / Sv[j];
                sc[j] = sqrtf(Qv[j]) * iv * iv;
            }
#pragma unroll
            for (int d = 0; d < 3; d++) {
                const float2 dA = unpack2(D2[d * 2]), dB = unpack2(D2[d * 2 + 1]);
                float4 o;
                o.x = dA.x * sc[0]; o.y = dA.y * sc[1];
                o.z = dB.x * sc[2]; o.w = dB.y * sc[3];
                *(float4*)&g_out_e[((size_t)(b * Nn + q) * 3 + d) * CEQ + cbase + c4 * 4] = o;
            }
        }
    } else {
        // ================= INV =================
        const int id = bx - 1024;
        const int hg = id & 1, qg = (id >> 1) & 63, b = id >> 7;
        const int h = lane & 7;
        const int hbase = hg * 8;
        const int q = qg * 4 + wid;

        {
            const int* arow = adj + (size_t)(b * Nn + q) * Nn;
            const int4 a0 = *(const int4*)&arow[lane * 8];
            const int4 a1 = *(const int4*)&arow[lane * 8 + 4];
            const bool c0 = a0.x != 0, c1 = a0.y != 0, c2 = a0.z != 0, c3 = a0.w != 0;
            const bool c5 = a1.x != 0, c6 = a1.y != 0, c7 = a1.z != 0, c8 = a1.w != 0;
            const unsigned any = __ballot_sync(0xffffffffu,
                c0 | c1 | c2 | c3 | c5 | c6 | c7 | c8);
            const float neg = any ? -1e30f : 0.0f;
            float4 m0, m1;
            m0.x = c0 ? 0.0f : neg; m0.y = c1 ? 0.0f : neg;
            m0.z = c2 ? 0.0f : neg; m0.w = c3 ? 0.0f : neg;
            m1.x = c5 ? 0.0f : neg; m1.y = c6 ? 0.0f : neg;
            m1.z = c7 ? 0.0f : neg; m1.w = c8 ? 0.0f : neg;
            *(float4*)&sm.i.mask[wid * 256 + lane * 8] = m0;
            *(float4*)&sm.i.mask[wid * 256 + lane * 8 + 4] = m1;
        }
        // prefetch tile 0: KTI*8h*16e = 2048 floats = 512 float4
#pragma unroll
        for (int r = 0; r < 4; r++) {
            const int j = t + r * 128;
            const int k = j >> 5, rem = j & 31;
            const int hh = rem >> 2, e4 = (rem & 3) * 4;
            cp16(&sm.i.hf[0][hh * 260 + k * 16 + e4],
                 &g_proj_i[(size_t)(b * Nn + k) * DIN + (hbase + hh) * 16 + e4]);
        }
        cp_commit();

        float S = 0.0f, SQ = 0.0f;
        u64 A2[8];
#pragma unroll
        for (int e = 0; e < 8; e++) A2[e] = 0ull;

        const float* imq = im + (size_t)(b * Nn + q) * (Nn * 16) + hbase + h;
        const float* mq = sm.i.mask + wid * 256;

        int buf = 0;
#pragma unroll 1
        for (int ti = 0; ti < Nn / KTI; ti++) {
            if (ti + 1 < Nn / KTI) {
                const int kb2 = (ti + 1) * KTI;
#pragma unroll
                for (int r = 0; r < 4; r++) {
                    const int j = t + r * 128;
                    const int k = j >> 5, rem = j & 31;
                    const int hh = rem >> 2, e4 = (rem & 3) * 4;
                    cp16(&sm.i.hf[buf ^ 1][hh * 260 + k * 16 + e4],
                         &g_proj_i[(size_t)(b * Nn + kb2 + k) * DIN + (hbase + hh) * 16 + e4]);
                }
                cp_commit();
                cp_wait<1>();
            } else {
                cp_wait<0>();
            }
            __syncthreads();
            const float* hs = sm.i.hf[buf];
            const int kb = ti * KTI;
#pragma unroll
            for (int it = 0; it < KTI / 4; it++) {
                const int kl = it * 4 + ksub;
                const int k = kb + kl;
                const float x = imq[(size_t)k * 16];
                const float p = ex2f(fmaf(x, L2E, mq[k]));
                S += p;
                SQ = fmaf(p, p, SQ);
                const u64 pp = pack2(p, p);
                const float* hk = hs + h * 260 + kl * 16;
                const ulonglong2 v0 = *(const ulonglong2*)&hk[0];
                const ulonglong2 v1 = *(const ulonglong2*)&hk[4];
                const ulonglong2 v2 = *(const ulonglong2*)&hk[8];
                const ulonglong2 v3 = *(const ulonglong2*)&hk[12];
                fma2(A2[0], pp, v0.x); fma2(A2[1], pp, v0.y);
                fma2(A2[2], pp, v1.x); fma2(A2[3], pp, v1.y);
                fma2(A2[4], pp, v2.x); fma2(A2[5], pp, v2.y);
                fma2(A2[6], pp, v3.x); fma2(A2[7], pp, v3.y);
            }
            __syncthreads();
            buf ^= 1;
        }

#pragma unroll
        for (int m = 8; m <= 16; m <<= 1) {
            S  += __shfl_xor_sync(0xffffffffu, S,  m);
            SQ += __shfl_xor_sync(0xffffffffu, SQ, m);
#pragma unroll
            for (int e = 0; e < 8; e++) {
                const u64 a = __shfl_xor_sync(0xffffffffu, A2[e], m);
                add2(A2[e], a);
            }
        }

        if (ksub == 0) {
            const float iv = 1.0f / S;
            const float sc = sqrtf(SQ) * iv * iv;
            float* o = g_out_i + (size_t)(b * Nn + q) * DIN + (hbase + h) * 16;
#pragma unroll
            for (int e4 = 0; e4 < 4; e4++) {
                const float2 lo = unpack2(A2[e4 * 2]);
                const float2 hi = unpack2(A2[e4 * 2 + 1]);
                float4 v;
                v.x = lo.x * sc; v.y = lo.y * sc;
                v.z = hi.x * sc; v.w = hi.y * sc;
                *(float4*)&o[e4 * 4] = v;
            }
        }
    }
}

// ---------------------------------------------------------------------------
// Output kernel: [0,96) equi out GEMM, [96,224) inv out GEMM
// ---------------------------------------------------------------------------
__global__ void __launch_bounds__(256) out_kernel(
    const float* __restrict__ W_equi_out, const float* __restrict__ b_equi_out,
    const float* __restrict__ W_out, const float* __restrict__ b_out,
    float* __restrict__ out)
{
    __shared__ __align__(16) float sm[4 * 16 * 68];
    const int bx = blockIdx.x;
    if (bx < 96) {
        gemm_tile(g_out_e, W_equi_out, b_equi_out, out, CEQ, CEQ, bx * 64, 0, sm);
    } else {
        const int id = bx - 96;
        gemm_tile(g_out_i, W_out, b_out, out + (size_t)Bsz * Nn * 3 * CEQ,
                  DIN, DIN, (id >> 2) * 64, (id & 3) * 64, sm);
    }
}

// ---------------------------------------------------------------------------
// Launch: 3 kernels
// ---------------------------------------------------------------------------
extern "C" void kernel_launch(void* const* d_in, const int* in_sizes, int n_in,
                              void* d_out, int out_size) {
    const float* v_equi     = (const float*)d_in[0];
    const float* v_inv      = (const float*)d_in[1];
    const float* em         = (const float*)d_in[2];
    const float* im         = (const float*)d_in[3];
    const int*   adj        = (const int*)  d_in[4];
    const float* W_coord    = (const float*)d_in[5];
    const float* W_equi_out = (const float*)d_in[6];
    const float* b_equi_out = (const float*)d_in[7];
    const float* W_in       = (const float*)d_in[8];
    const float* b_in       = (const float*)d_in[9];
    const float* W_out      = (const float*)d_in[10];
    const float* b_out      = (const float*)d_in[11];
    float* out = (float*)d_out;

    prep_kernel<<<224, 256>>>(v_equi, v_inv, W_coord, W_in, b_in);
    attn_kernel<<<2048, 128>>>(em, im, adj);
    out_kernel<<<224, 256>>>(W_equi_out, b_equi_out, W_out, b_out, out);
}

// round 11
// speedup vs baseline: 1.5852x; 1.0944x over previous
#include <cuda_runtime.h>
#include <cuda_bf16.h>
#include <cstdint>

// ---------------------------------------------------------------------------
// SemlaLayer: equi + inv attention, B=8, N=256, D_EQUI=64, H=16, D_HEAD=16
// ---------------------------------------------------------------------------
#define Bsz 8
#define Nn  256
#define CEQ 64
#define DIN 256
#define L2E 1.4426950408889634f
#define KT  32
#define KTI 16

typedef unsigned long long u64;

// Scratch (device globals; no allocation allowed)
__device__ __align__(128) float g_proj_e[Bsz * Nn * 3 * CEQ];
__device__ __align__(128) float g_proj_i[Bsz * Nn * DIN];
__device__ __align__(128) float g_out_e [Bsz * Nn * 3 * CEQ];
__device__ __align__(128) float g_out_i [Bsz * Nn * DIN];

__device__ __forceinline__ float ex2f(float x) {
    float r;
    asm("ex2.approx.ftz.f32 %0, %1;" : "=f"(r) : "f"(x));
    return r;
}
__device__ __forceinline__ u64 pack2(float lo, float hi) {
    u64 r;
    asm("mov.b64 %0, {%1, %2};" : "=l"(r) : "f"(lo), "f"(hi));
    return r;
}
__device__ __forceinline__ float2 unpack2(u64 v) {
    float2 f;
    asm("mov.b64 {%0, %1}, %2;" : "=f"(f.x), "=f"(f.y) : "l"(v));
    return f;
}
__device__ __forceinline__ void fma2(u64& d, u64 a, u64 b) {
    asm("fma.rn.f32x2 %0, %1, %2, %3;" : "=l"(d) : "l"(a), "l"(b), "l"(d));
}
__device__ __forceinline__ void add2(u64& d, u64 a) {
    asm("add.rn.f32x2 %0, %1, %2;" : "=l"(d) : "l"(a), "l"(d));
}

__device__ __forceinline__ void cp16(float* dst_smem, const float* src) {
    uint32_t d = (uint32_t)__cvta_generic_to_shared(dst_smem);
    asm volatile("cp.async.cg.shared.global [%0], [%1], 16;" :: "r"(d), "l"(src) : "memory");
}
__device__ __forceinline__ void cp_commit() {
    asm volatile("cp.async.commit_group;" ::: "memory");
}
template <int N> __device__ __forceinline__ void cp_wait() {
    asm volatile("cp.async.wait_group %0;" :: "n"(N) : "memory");
}

// ---------------------------------------------------------------------------
// Pipelined GEMM tile: C[m_base:+32, n_base:+64] = X @ W^T (+bias)
// 256 threads, BK=16, double-buffered smem, 2x4 microtile.
// sm: 2*(16*36 + 16*68) floats = 13.3 KB.
// ---------------------------------------------------------------------------
__device__ __forceinline__ void gemm_tile32(
    const float* __restrict__ X, const float* __restrict__ W,
    const float* __restrict__ bias, float* __restrict__ C,
    int Nout, int K, int m_base, int n_base, float* sm)
{
    const int t = threadIdx.x;
    const int tx = t & 15, ty = t >> 4;
    const int lm = t >> 2;
    const int lk = (t & 3) * 4;

    float acc[2][4];
#pragma unroll
    for (int i = 0; i < 2; i++)
#pragma unroll
        for (int j = 0; j < 4; j++) acc[i][j] = 0.0f;

    // buffer b: Xs = sm + b*1664 (16x36), Ws = sm + b*1664 + 576 (16x68)
    {
        float* Xs = sm;
        float* Ws = sm + 576;
        if (t < 128) {
            float4 vx = *(const float4*)&X[(size_t)(m_base + lm) * K + lk];
            Xs[(lk + 0) * 36 + lm] = vx.x; Xs[(lk + 1) * 36 + lm] = vx.y;
            Xs[(lk + 2) * 36 + lm] = vx.z; Xs[(lk + 3) * 36 + lm] = vx.w;
        }
        float4 vw = *(const float4*)&W[(size_t)(n_base + lm) * K + lk];
        Ws[(lk + 0) * 68 + lm] = vw.x; Ws[(lk + 1) * 68 + lm] = vw.y;
        Ws[(lk + 2) * 68 + lm] = vw.z; Ws[(lk + 3) * 68 + lm] = vw.w;
    }
    __syncthreads();

    const int nsteps = K / 16;
    for (int s = 0; s < nsteps; s++) {
        float4 nx, nw;
        const bool more = (s + 1 < nsteps);
        if (more) {
            if (t < 128)
                nx = *(const float4*)&X[(size_t)(m_base + lm) * K + (s + 1) * 16 + lk];
            nw = *(const float4*)&W[(size_t)(n_base + lm) * K + (s + 1) * 16 + lk];
        }
        const float* Xs = sm + (s & 1) * 1664;
        const float* Ws = Xs + 576;
#pragma unroll
        for (int kk = 0; kk < 16; kk++) {
            const float2 av = *(const float2*)&Xs[kk * 36 + ty * 2];
            const float4 bv = *(const float4*)&Ws[kk * 68 + tx * 4];
            const float a[2] = {av.x, av.y};
            const float b[4] = {bv.x, bv.y, bv.z, bv.w};
#pragma unroll
            for (int i = 0; i < 2; i++)
#pragma unroll
                for (int j = 0; j < 4; j++) acc[i][j] = fmaf(a[i], b[j], acc[i][j]);
        }
        if (more) {
            float* Xd = sm + ((s + 1) & 1) * 1664;
            float* Wd = Xd + 576;
            if (t < 128) {
                Xd[(lk + 0) * 36 + lm] = nx.x; Xd[(lk + 1) * 36 + lm] = nx.y;
                Xd[(lk + 2) * 36 + lm] = nx.z; Xd[(lk + 3) * 36 + lm] = nx.w;
            }
            Wd[(lk + 0) * 68 + lm] = nw.x; Wd[(lk + 1) * 68 + lm] = nw.y;
            Wd[(lk + 2) * 68 + lm] = nw.z; Wd[(lk + 3) * 68 + lm] = nw.w;
        }
        __syncthreads();
    }
#pragma unroll
    for (int i = 0; i < 2; i++) {
        const int m = m_base + ty * 2 + i;
#pragma unroll
        for (int j = 0; j < 4; j++) {
            const int n = n_base + tx * 4 + j;
            const float bv = bias ? bias[n] : 0.0f;
            C[(size_t)m * Nout + n] = acc[i][j] + bv;
        }
    }
}

// ---------------------------------------------------------------------------
// Prep kernel: [0,192) equi input GEMM, [192,448) inv input GEMM
// ---------------------------------------------------------------------------
__global__ void __launch_bounds__(256) prep_kernel(
    const float* __restrict__ v_equi, const float* __restrict__ v_inv,
    const float* __restrict__ W_coord,
    const float* __restrict__ W_in, const float* __restrict__ b_in)
{
    __shared__ __align__(16) float sm[2 * (16 * 36 + 16 * 68)];
    const int bx = blockIdx.x;
    if (bx < 192) {
        gemm_tile32(v_equi, W_coord, nullptr, g_proj_e, CEQ, CEQ, bx * 32, 0, sm);
    } else {
        const int id = bx - 192;                // 64 m-tiles x 4 n-tiles
        gemm_tile32(v_inv, W_in, b_in, g_proj_i, DIN, DIN, (id >> 2) * 32, (id & 3) * 64, sm);
    }
}

// ---------------------------------------------------------------------------
// Fused attention kernel. 128 threads (4 warps), each warp owns TWO q.
// blockIdx.x < 512: equi;  >= 512: inv. Mask computed in-kernel from adj.
// cp.async double-buffered k-tiles; all accumulator math packed f32x2.
// ---------------------------------------------------------------------------
union __align__(16) AttnSm {
    struct { float proj[2][KT * 96];  float mask[8 * 256]; } e;   // 32 KB
    struct { float hf[2][8 * 260];    float mask[8 * 256]; } i;   // 24.6 KB
};

__global__ void __launch_bounds__(128, 4) attn_kernel(
    const float* __restrict__ em,      // [B,N,N,64]
    const float* __restrict__ im,      // [B,N,N,16]
    const int*   __restrict__ adj)     // [B,N,N]
{
    __shared__ AttnSm sm;
    const int bx = blockIdx.x;
    const int t = threadIdx.x;
    const int wid = t >> 5, lane = t & 31;
    const int ksub = lane >> 3;

    if (bx < 512) {
        // ================= EQUI =================
        const int cg = bx & 1, qg = (bx >> 1) & 31, b = bx >> 6;
        const int c4 = lane & 7;
        const int cbase = cg * 32;
        const int q0 = qg * 8 + wid * 2;

        // mask from adj: warp computes its 2 q-rows
#pragma unroll
        for (int j = 0; j < 2; j++) {
            const int* arow = adj + (size_t)(b * Nn + q0 + j) * Nn;
            const int4 a0 = *(const int4*)&arow[lane * 8];
            const int4 a1 = *(const int4*)&arow[lane * 8 + 4];
            const bool c0 = a0.x != 0, c1 = a0.y != 0, c2 = a0.z != 0, c3 = a0.w != 0;
            const bool c5 = a1.x != 0, c6 = a1.y != 0, c7 = a1.z != 0, c8 = a1.w != 0;
            const unsigned any = __ballot_sync(0xffffffffu,
                c0 | c1 | c2 | c3 | c5 | c6 | c7 | c8);
            const float neg = any ? -1e30f : 0.0f;
            float4 m0, m1;
            m0.x = c0 ? 0.0f : neg; m0.y = c1 ? 0.0f : neg;
            m0.z = c2 ? 0.0f : neg; m0.w = c3 ? 0.0f : neg;
            m1.x = c5 ? 0.0f : neg; m1.y = c6 ? 0.0f : neg;
            m1.z = c7 ? 0.0f : neg; m1.w = c8 ? 0.0f : neg;
            *(float4*)&sm.e.mask[(wid * 2 + j) * 256 + lane * 8] = m0;
            *(float4*)&sm.e.mask[(wid * 2 + j) * 256 + lane * 8 + 4] = m1;
        }
        // prefetch tile 0
#pragma unroll
        for (int r = 0; r < 6; r++) {
            const int j = t + r * 128;
            const int k = j / 24, rem = j - k * 24;
            const int d = rem >> 3, cl = (rem & 7) * 4;
            cp16(&sm.e.proj[0][k * 96 + d * 32 + cl],
                 &g_proj_e[((size_t)(b * Nn + k) * 3 + d) * CEQ + cbase + cl]);
        }
        cp_commit();

        u64 Sa[2], Qa[2], Da[6], Sb[2], Qb[2], Db[6];
#pragma unroll
        for (int j = 0; j < 2; j++) { Sa[j] = Qa[j] = Sb[j] = Qb[j] = 0ull; }
#pragma unroll
        for (int r = 0; r < 6; r++) { Da[r] = 0ull; Db[r] = 0ull; }

        const float* emq0 = em + (size_t)(b * Nn + q0) * (Nn * CEQ) + cbase;
        const float* emq1 = emq0 + Nn * CEQ;
        const float* mq0 = sm.e.mask + (wid * 2) * 256;
        const float* mq1 = mq0 + 256;

        int buf = 0;
#pragma unroll 1
        for (int ti = 0; ti < Nn / KT; ti++) {
            if (ti + 1 < Nn / KT) {
                const int kb2 = (ti + 1) * KT;
#pragma unroll
                for (int r = 0; r < 6; r++) {
                    const int j = t + r * 128;
                    const int k = j / 24, rem = j - k * 24;
                    const int d = rem >> 3, cl = (rem & 7) * 4;
                    cp16(&sm.e.proj[buf ^ 1][k * 96 + d * 32 + cl],
                         &g_proj_e[((size_t)(b * Nn + kb2 + k) * 3 + d) * CEQ + cbase + cl]);
                }
                cp_commit();
                cp_wait<1>();
            } else {
                cp_wait<0>();
            }
            __syncthreads();
            const float* ps = sm.e.proj[buf];
            const int kb = ti * KT;
#pragma unroll
            for (int it = 0; it < KT / 4; it++) {
                const int kl = it * 4 + ksub;
                const int k = kb + kl;
                const float4 x0 = *(const float4*)&emq0[(size_t)k * CEQ + c4 * 4];
                const float4 x1 = *(const float4*)&emq1[(size_t)k * CEQ + c4 * 4];
                const float mk0 = mq0[k], mk1 = mq1[k];
                const float a0 = ex2f(fmaf(x0.x, L2E, mk0));
                const float a1 = ex2f(fmaf(x0.y, L2E, mk0));
                const float a2 = ex2f(fmaf(x0.z, L2E, mk0));
                const float a3 = ex2f(fmaf(x0.w, L2E, mk0));
                const float b0 = ex2f(fmaf(x1.x, L2E, mk1));
                const float b1 = ex2f(fmaf(x1.y, L2E, mk1));
                const float b2 = ex2f(fmaf(x1.z, L2E, mk1));
                const float b3 = ex2f(fmaf(x1.w, L2E, mk1));
                const u64 pA0 = pack2(a0, a1), pB0 = pack2(a2, a3);
                const u64 pA1 = pack2(b0, b1), pB1 = pack2(b2, b3);
                add2(Sa[0], pA0);      add2(Sa[1], pB0);
                add2(Sb[0], pA1);      add2(Sb[1], pB1);
                fma2(Qa[0], pA0, pA0); fma2(Qa[1], pB0, pB0);
                fma2(Qb[0], pA1, pA1); fma2(Qb[1], pB1, pB1);
                const ulonglong2 va = *(const ulonglong2*)&ps[kl * 96 +  0 + c4 * 4];
                const ulonglong2 vb = *(const ulonglong2*)&ps[kl * 96 + 32 + c4 * 4];
                const ulonglong2 vc = *(const ulonglong2*)&ps[kl * 96 + 64 + c4 * 4];
                fma2(Da[0], pA0, va.x); fma2(Da[1], pB0, va.y);
                fma2(Da[2], pA0, vb.x); fma2(Da[3], pB0, vb.y);
                fma2(Da[4], pA0, vc.x); fma2(Da[5], pB0, vc.y);
                fma2(Db[0], pA1, va.x); fma2(Db[1], pB1, va.y);
                fma2(Db[2], pA1, vb.x); fma2(Db[3], pB1, vb.y);
                fma2(Db[4], pA1, vc.x); fma2(Db[5], pB1, vc.y);
            }
            __syncthreads();
            buf ^= 1;
        }

#pragma unroll
        for (int m = 8; m <= 16; m <<= 1) {
#pragma unroll
            for (int j = 0; j < 2; j++) {
                u64 v;
                v = __shfl_xor_sync(0xffffffffu, Sa[j], m); add2(Sa[j], v);
                v = __shfl_xor_sync(0xffffffffu, Qa[j], m); add2(Qa[j], v);
                v = __shfl_xor_sync(0xffffffffu, Sb[j], m); add2(Sb[j], v);
                v = __shfl_xor_sync(0xffffffffu, Qb[j], m); add2(Qb[j], v);
            }
#pragma unroll
            for (int r = 0; r < 6; r++) {
                u64 v;
                v = __shfl_xor_sync(0xffffffffu, Da[r], m); add2(Da[r], v);
                v = __shfl_xor_sync(0xffffffffu, Db[r], m); add2(Db[r], v);
            }
        }

        if (ksub == 0) {
#pragma unroll
            for (int qq = 0; qq < 2; qq++) {
                const u64* S2 = qq ? Sb : Sa;
                const u64* Q2 = qq ? Qb : Qa;
                const u64* D2 = qq ? Db : Da;
                const float2 sA = unpack2(S2[0]), sB = unpack2(S2[1]);
                const float2 qA = unpack2(Q2[0]), qB = unpack2(Q2[1]);
                const float Sv[4] = {sA.x, sA.y, sB.x, sB.y};
                const float Qv[4] = {qA.x, qA.y, qB.x, qB.y};
                float sc[4];
#pragma unroll
                for (int j = 0; j < 4; j++) {
                    const float iv = 1.0f / Sv[j];
                    sc[j] = sqrtf(Qv[j]) * iv * iv;
                }
#pragma unroll
                for (int d = 0; d < 3; d++) {
                    const float2 dA = unpack2(D2[d * 2]), dB = unpack2(D2[d * 2 + 1]);
                    float4 o;
                    o.x = dA.x * sc[0]; o.y = dA.y * sc[1];
                    o.z = dB.x * sc[2]; o.w = dB.y * sc[3];
                    *(float4*)&g_out_e[((size_t)(b * Nn + q0 + qq) * 3 + d) * CEQ + cbase + c4 * 4] = o;
                }
            }
        }
    } else {
        // ================= INV =================
        const int id = bx - 512;
        const int hg = id & 1, qg = (id >> 1) & 31, b = id >> 6;
        const int h = lane & 7;
        const int hbase = hg * 8;
        const int q0 = qg * 8 + wid * 2;

#pragma unroll
        for (int j = 0; j < 2; j++) {
            const int* arow = adj + (size_t)(b * Nn + q0 + j) * Nn;
            const int4 a0 = *(const int4*)&arow[lane * 8];
            const int4 a1 = *(const int4*)&arow[lane * 8 + 4];
            const bool c0 = a0.x != 0, c1 = a0.y != 0, c2 = a0.z != 0, c3 = a0.w != 0;
            const bool c5 = a1.x != 0, c6 = a1.y != 0, c7 = a1.z != 0, c8 = a1.w != 0;
            const unsigned any = __ballot_sync(0xffffffffu,
                c0 | c1 | c2 | c3 | c5 | c6 | c7 | c8);
            const float neg = any ? -1e30f : 0.0f;
            float4 m0, m1;
            m0.x = c0 ? 0.0f : neg; m0.y = c1 ? 0.0f : neg;
            m0.z = c2 ? 0.0f : neg; m0.w = c3 ? 0.0f : neg;
            m1.x = c5 ? 0.0f : neg; m1.y = c6 ? 0.0f : neg;
            m1.z = c7 ? 0.0f : neg; m1.w = c8 ? 0.0f : neg;
            *(float4*)&sm.i.mask[(wid * 2 + j) * 256 + lane * 8] = m0;
            *(float4*)&sm.i.mask[(wid * 2 + j) * 256 + lane * 8 + 4] = m1;
        }
        // prefetch tile 0: KTI*8h*16e = 2048 floats = 512 float4
#pragma unroll
        for (int r = 0; r < 4; r++) {
            const int j = t + r * 128;
            const int k = j >> 5, rem = j & 31;
            const int hh = rem >> 2, e4 = (rem & 3) * 4;
            cp16(&sm.i.hf[0][hh * 260 + k * 16 + e4],
                 &g_proj_i[(size_t)(b * Nn + k) * DIN + (hbase + hh) * 16 + e4]);
        }
        cp_commit();

        float S0 = 0.0f, SQ0 = 0.0f, S1 = 0.0f, SQ1 = 0.0f;
        u64 Aa[8], Ab[8];
#pragma unroll
        for (int e = 0; e < 8; e++) { Aa[e] = 0ull; Ab[e] = 0ull; }

        const float* imq0 = im + (size_t)(b * Nn + q0) * (Nn * 16) + hbase + h;
        const float* imq1 = imq0 + Nn * 16;
        const float* mq0 = sm.i.mask + (wid * 2) * 256;
        const float* mq1 = mq0 + 256;

        int buf = 0;
#pragma unroll 1
        for (int ti = 0; ti < Nn / KTI; ti++) {
            if (ti + 1 < Nn / KTI) {
                const int kb2 = (ti + 1) * KTI;
#pragma unroll
                for (int r = 0; r < 4; r++) {
                    const int j = t + r * 128;
                    const int k = j >> 5, rem = j & 31;
                    const int hh = rem >> 2, e4 = (rem & 3) * 4;
                    cp16(&sm.i.hf[buf ^ 1][hh * 260 + k * 16 + e4],
                         &g_proj_i[(size_t)(b * Nn + kb2 + k) * DIN + (hbase + hh) * 16 + e4]);
                }
                cp_commit();
                cp_wait<1>();
            } else {
                cp_wait<0>();
            }
            __syncthreads();
            const float* hs = sm.i.hf[buf];
            const int kb = ti * KTI;
#pragma unroll
            for (int it = 0; it < KTI / 4; it++) {
                const int kl = it * 4 + ksub;
                const int k = kb + kl;
                const float x0 = imq0[(size_t)k * 16];
                const float x1 = imq1[(size_t)k * 16];
                const float p0 = ex2f(fmaf(x0, L2E, mq0[k]));
                const float p1 = ex2f(fmaf(x1, L2E, mq1[k]));
                S0 += p0; SQ0 = fmaf(p0, p0, SQ0);
                S1 += p1; SQ1 = fmaf(p1, p1, SQ1);
                const u64 pp0 = pack2(p0, p0);
                const u64 pp1 = pack2(p1, p1);
                const float* hk = hs + h * 260 + kl * 16;
                const ulonglong2 v0 = *(const ulonglong2*)&hk[0];
                const ulonglong2 v1 = *(const ulonglong2*)&hk[4];
                const ulonglong2 v2 = *(const ulonglong2*)&hk[8];
                const ulonglong2 v3 = *(const ulonglong2*)&hk[12];
                fma2(Aa[0], pp0, v0.x); fma2(Aa[1], pp0, v0.y);
                fma2(Aa[2], pp0, v1.x); fma2(Aa[3], pp0, v1.y);
                fma2(Aa[4], pp0, v2.x); fma2(Aa[5], pp0, v2.y);
                fma2(Aa[6], pp0, v3.x); fma2(Aa[7], pp0, v3.y);
                fma2(Ab[0], pp1, v0.x); fma2(Ab[1], pp1, v0.y);
                fma2(Ab[2], pp1, v1.x); fma2(Ab[3], pp1, v1.y);
                fma2(Ab[4], pp1, v2.x); fma2(Ab[5], pp1, v2.y);
                fma2(Ab[6], pp1, v3.x); fma2(Ab[7], pp1, v3.y);
            }
            __syncthreads();
            buf ^= 1;
        }

#pragma unroll
        for (int m = 8; m <= 16; m <<= 1) {
            S0  += __shfl_xor_sync(0xffffffffu, S0,  m);
            SQ0 += __shfl_xor_sync(0xffffffffu, SQ0, m);
            S1  += __shfl_xor_sync(0xffffffffu, S1,  m);
            SQ1 += __shfl_xor_sync(0xffffffffu, SQ1, m);
#pragma unroll
            for (int e = 0; e < 8; e++) {
                u64 v;
                v = __shfl_xor_sync(0xffffffffu, Aa[e], m); add2(Aa[e], v);
                v = __shfl_xor_sync(0xffffffffu, Ab[e], m); add2(Ab[e], v);
            }
        }

        if (ksub == 0) {
            const float i0 = 1.0f / S0, i1 = 1.0f / S1;
            const float sc0 = sqrtf(SQ0) * i0 * i0;
            const float sc1 = sqrtf(SQ1) * i1 * i1;
            float* o0 = g_out_i + (size_t)(b * Nn + q0) * DIN + (hbase + h) * 16;
            float* o1 = o0 + DIN;
#pragma unroll
            for (int e4 = 0; e4 < 4; e4++) {
                const float2 lo0 = unpack2(Aa[e4 * 2]);
                const float2 hi0 = unpack2(Aa[e4 * 2 + 1]);
                const float2 lo1 = unpack2(Ab[e4 * 2]);
                const float2 hi1 = unpack2(Ab[e4 * 2 + 1]);
                float4 v0, v1;
                v0.x = lo0.x * sc0; v0.y = lo0.y * sc0;
                v0.z = hi0.x * sc0; v0.w = hi0.y * sc0;
                v1.x = lo1.x * sc1; v1.y = lo1.y * sc1;
                v1.z = hi1.x * sc1; v1.w = hi1.y * sc1;
                *(float4*)&o0[e4 * 4] = v0;
                *(float4*)&o1[e4 * 4] = v1;
            }
        }
    }
}

// ---------------------------------------------------------------------------
// Output kernel: [0,192) equi out GEMM, [192,448) inv out GEMM
// ---------------------------------------------------------------------------
__global__ void __launch_bounds__(256) out_kernel(
    const float* __restrict__ W_equi_out, const float* __restrict__ b_equi_out,
    const float* __restrict__ W_out, const float* __restrict__ b_out,
    float* __restrict__ out)
{
    __shared__ __align__(16) float sm[2 * (16 * 36 + 16 * 68)];
    const int bx = blockIdx.x;
    if (bx < 192) {
        gemm_tile32(g_out_e, W_equi_out, b_equi_out, out, CEQ, CEQ, bx * 32, 0, sm);
    } else {
        const int id = bx - 192;
        gemm_tile32(g_out_i, W_out, b_out, out + (size_t)Bsz * Nn * 3 * CEQ,
                    DIN, DIN, (id >> 2) * 32, (id & 3) * 64, sm);
    }
}

// ---------------------------------------------------------------------------
// Launch: 3 kernels
// ---------------------------------------------------------------------------
extern "C" void kernel_launch(void* const* d_in, const int* in_sizes, int n_in,
                              void* d_out, int out_size) {
    const float* v_equi     = (const float*)d_in[0];
    const float* v_inv      = (const float*)d_in[1];
    const float* em         = (const float*)d_in[2];
    const float* im         = (const float*)d_in[3];
    const int*   adj        = (const int*)  d_in[4];
    const float* W_coord    = (const float*)d_in[5];
    const float* W_equi_out = (const float*)d_in[6];
    const float* b_equi_out = (const float*)d_in[7];
    const float* W_in       = (const float*)d_in[8];
    const float* b_in       = (const float*)d_in[9];
    const float* W_out      = (const float*)d_in[10];
    const float* b_out      = (const float*)d_in[11];
    float* out = (float*)d_out;

    prep_kernel<<<448, 256>>>(v_equi, v_inv, W_coord, W_in, b_in);
    attn_kernel<<<1024, 128>>>(em, im, adj);
    out_kernel<<<448, 256>>>(W_equi_out, b_equi_out, W_out, b_out, out);
}

// round 12
// speedup vs baseline: 1.6087x; 1.0148x over previous
#include <cuda_runtime.h>
#include <cuda_bf16.h>
#include <cstdint>

// ---------------------------------------------------------------------------
// SemlaLayer: equi + inv attention, B=8, N=256, D_EQUI=64, H=16, D_HEAD=16
// ---------------------------------------------------------------------------
#define Bsz 8
#define Nn  256
#define CEQ 64
#define DIN 256
#define L2E 1.4426950408889634f
#define KTE 16
#define KTI 16

typedef unsigned long long u64;

// Scratch (device globals; no allocation allowed)
__device__ __align__(128) float g_proj_e[Bsz * Nn * 3 * CEQ];
__device__ __align__(128) float g_proj_i[Bsz * Nn * DIN];
__device__ __align__(128) float g_out_i [Bsz * Nn * DIN];

__device__ __forceinline__ float ex2f(float x) {
    float r;
    asm("ex2.approx.ftz.f32 %0, %1;" : "=f"(r) : "f"(x));
    return r;
}
__device__ __forceinline__ u64 pack2(float lo, float hi) {
    u64 r;
    asm("mov.b64 %0, {%1, %2};" : "=l"(r) : "f"(lo), "f"(hi));
    return r;
}
__device__ __forceinline__ float2 unpack2(u64 v) {
    float2 f;
    asm("mov.b64 {%0, %1}, %2;" : "=f"(f.x), "=f"(f.y) : "l"(v));
    return f;
}
__device__ __forceinline__ void fma2(u64& d, u64 a, u64 b) {
    asm("fma.rn.f32x2 %0, %1, %2, %3;" : "=l"(d) : "l"(a), "l"(b), "l"(d));
}
__device__ __forceinline__ void add2(u64& d, u64 a) {
    asm("add.rn.f32x2 %0, %1, %2;" : "=l"(d) : "l"(a), "l"(d));
}

__device__ __forceinline__ void cp16(float* dst_smem, const float* src) {
    uint32_t d = (uint32_t)__cvta_generic_to_shared(dst_smem);
    asm volatile("cp.async.cg.shared.global [%0], [%1], 16;" :: "r"(d), "l"(src) : "memory");
}
__device__ __forceinline__ void cp_commit() {
    asm volatile("cp.async.commit_group;" ::: "memory");
}
template <int N> __device__ __forceinline__ void cp_wait() {
    asm volatile("cp.async.wait_group %0;" :: "n"(N) : "memory");
}

// ---------------------------------------------------------------------------
// f32x2 GEMM tile: C[m_base:+64, n_base:+64] = X @ W^T (+bias)
// 256 threads, BK=16, double-buffered smem, packed row-pair accumulators.
// sm: 2*2*16*68 floats (17.4 KB).
// ---------------------------------------------------------------------------
__device__ __forceinline__ void gemm_tile64(
    const float* __restrict__ X, const float* __restrict__ W,
    const float* __restrict__ bias, float* __restrict__ C,
    int Nout, int K, int m_base, int n_base, float* sm)
{
    const int t = threadIdx.x;
    const int tx = t & 15, ty = t >> 4;
    const int lm = t >> 2;
    const int lk = (t & 3) * 4;

    u64 acc[2][4];
#pragma unroll
    for (int i = 0; i < 2; i++)
#pragma unroll
        for (int j = 0; j < 4; j++) acc[i][j] = 0ull;

    {
        float4 vx = *(const float4*)&X[(size_t)(m_base + lm) * K + lk];
        float4 vw = *(const float4*)&W[(size_t)(n_base + lm) * K + lk];
        float* Xs = sm;
        float* Ws = sm + 1088;
        Xs[(lk + 0) * 68 + lm] = vx.x; Xs[(lk + 1) * 68 + lm] = vx.y;
        Xs[(lk + 2) * 68 + lm] = vx.z; Xs[(lk + 3) * 68 + lm] = vx.w;
        Ws[(lk + 0) * 68 + lm] = vw.x; Ws[(lk + 1) * 68 + lm] = vw.y;
        Ws[(lk + 2) * 68 + lm] = vw.z; Ws[(lk + 3) * 68 + lm] = vw.w;
    }
    __syncthreads();

    const int nsteps = K / 16;
    for (int s = 0; s < nsteps; s++) {
        float4 nx, nw;
        const bool more = (s + 1 < nsteps);
        if (more) {
            nx = *(const float4*)&X[(size_t)(m_base + lm) * K + (s + 1) * 16 + lk];
            nw = *(const float4*)&W[(size_t)(n_base + lm) * K + (s + 1) * 16 + lk];
        }
        const float* Xs = sm + (s & 1) * 2176;
        const float* Ws = Xs + 1088;
#pragma unroll
        for (int kk = 0; kk < 16; kk++) {
            const ulonglong2 ax = *(const ulonglong2*)&Xs[kk * 68 + ty * 4];
            const float4 bv = *(const float4*)&Ws[kk * 68 + tx * 4];
            const u64 b0 = pack2(bv.x, bv.x), b1 = pack2(bv.y, bv.y);
            const u64 b2 = pack2(bv.z, bv.z), b3 = pack2(bv.w, bv.w);
            fma2(acc[0][0], ax.x, b0); fma2(acc[0][1], ax.x, b1);
            fma2(acc[0][2], ax.x, b2); fma2(acc[0][3], ax.x, b3);
            fma2(acc[1][0], ax.y, b0); fma2(acc[1][1], ax.y, b1);
            fma2(acc[1][2], ax.y, b2); fma2(acc[1][3], ax.y, b3);
        }
        if (more) {
            float* Xd = sm + ((s + 1) & 1) * 2176;
            float* Wd = Xd + 1088;
            Xd[(lk + 0) * 68 + lm] = nx.x; Xd[(lk + 1) * 68 + lm] = nx.y;
            Xd[(lk + 2) * 68 + lm] = nx.z; Xd[(lk + 3) * 68 + lm] = nx.w;
            Wd[(lk + 0) * 68 + lm] = nw.x; Wd[(lk + 1) * 68 + lm] = nw.y;
            Wd[(lk + 2) * 68 + lm] = nw.z; Wd[(lk + 3) * 68 + lm] = nw.w;
        }
        __syncthreads();
    }

    float4 bvec;
    if (bias) bvec = *(const float4*)&bias[n_base + tx * 4];
    else      bvec = make_float4(0.f, 0.f, 0.f, 0.f);
#pragma unroll
    for (int p = 0; p < 2; p++) {
        float4 lo, hi;
        float2 f;
        f = unpack2(acc[p][0]); lo.x = f.x + bvec.x; hi.x = f.y + bvec.x;
        f = unpack2(acc[p][1]); lo.y = f.x + bvec.y; hi.y = f.y + bvec.y;
        f = unpack2(acc[p][2]); lo.z = f.x + bvec.z; hi.z = f.y + bvec.z;
        f = unpack2(acc[p][3]); lo.w = f.x + bvec.w; hi.w = f.y + bvec.w;
        const int m = m_base + ty * 4 + p * 2;
        *(float4*)&C[(size_t)m * Nout + n_base + tx * 4] = lo;
        *(float4*)&C[(size_t)(m + 1) * Nout + n_base + tx * 4] = hi;
    }
}

// ---------------------------------------------------------------------------
// Prep kernel: [0,96) equi input GEMM, [96,224) inv input GEMM
// ---------------------------------------------------------------------------
__global__ void __launch_bounds__(256) prep_kernel(
    const float* __restrict__ v_equi, const float* __restrict__ v_inv,
    const float* __restrict__ W_coord,
    const float* __restrict__ W_in, const float* __restrict__ b_in)
{
    __shared__ __align__(16) float sm[2 * 2 * 16 * 68];
    const int bx = blockIdx.x;
    if (bx < 96) {
        gemm_tile64(v_equi, W_coord, nullptr, g_proj_e, CEQ, CEQ, bx * 64, 0, sm);
    } else {
        const int id = bx - 96;                 // 32 m-tiles x 4 n-tiles
        gemm_tile64(v_inv, W_in, b_in, g_proj_i, DIN, DIN, (id >> 2) * 64, (id & 3) * 64, sm);
    }
}

// ---------------------------------------------------------------------------
// Fused attention kernel. 128 threads (4 warps), each warp owns TWO q.
// blockIdx.x < 256: equi (full 64 channels, fused output projection);
// >= 256: inv. Mask computed in-kernel from adj. cp.async double-buffered
// k-tiles; all accumulator math packed f32x2.
// ---------------------------------------------------------------------------
union __align__(16) AttnSm {
    struct { float proj[2 * KTE * 192]; float mask[8 * 256]; } e;  // 32.8 KB
    struct { float hf[2][8 * 260];      float mask[8 * 256]; } i;  // 24.8 KB
};

__global__ void __launch_bounds__(128, 4) attn_kernel(
    const float* __restrict__ em,      // [B,N,N,64]
    const float* __restrict__ im,      // [B,N,N,16]
    const int*   __restrict__ adj,     // [B,N,N]
    const float* __restrict__ W_eo,    // [64,64]
    const float* __restrict__ b_eo,    // [64]
    float* __restrict__ out_equi)      // d_out equi part [B,N,3,64]
{
    __shared__ AttnSm sm;
    const int bx = blockIdx.x;
    const int t = threadIdx.x;
    const int wid = t >> 5, lane = t & 31;

    if (bx < 256) {
        // ================= EQUI (full 64 channels) =================
        const int qg = bx & 31, b = bx >> 5;
        const int c4 = lane & 15;          // 16 chunks x 4 floats = 64 channels
        const int ksub = lane >> 4;        // 0..1
        const int q0 = qg * 8 + wid * 2;

        // mask from adj: warp computes its 2 q-rows
#pragma unroll
        for (int j = 0; j < 2; j++) {
            const int* arow = adj + (size_t)(b * Nn + q0 + j) * Nn;
            const int4 a0 = *(const int4*)&arow[lane * 8];
            const int4 a1 = *(const int4*)&arow[lane * 8 + 4];
            const bool c0 = a0.x != 0, c1 = a0.y != 0, c2 = a0.z != 0, c3 = a0.w != 0;
            const bool c5 = a1.x != 0, c6 = a1.y != 0, c7 = a1.z != 0, c8 = a1.w != 0;
            const unsigned any = __ballot_sync(0xffffffffu,
                c0 | c1 | c2 | c3 | c5 | c6 | c7 | c8);
            const float neg = any ? -1e30f : 0.0f;
            float4 m0, m1;
            m0.x = c0 ? 0.0f : neg; m0.y = c1 ? 0.0f : neg;
            m0.z = c2 ? 0.0f : neg; m0.w = c3 ? 0.0f : neg;
            m1.x = c5 ? 0.0f : neg; m1.y = c6 ? 0.0f : neg;
            m1.z = c7 ? 0.0f : neg; m1.w = c8 ? 0.0f : neg;
            *(float4*)&sm.e.mask[(wid * 2 + j) * 256 + lane * 8] = m0;
            *(float4*)&sm.e.mask[(wid * 2 + j) * 256 + lane * 8 + 4] = m1;
        }
        // prefetch tile 0: KTE*3*64 = 3072 floats = 768 float4, 6 per thread
#pragma unroll
        for (int r = 0; r < 6; r++) {
            const int j = t + r * 128;
            const int k = j / 48, rem = j % 48;
            const int d = rem >> 4, cl = (rem & 15) * 4;
            cp16(&sm.e.proj[k * 192 + d * 64 + cl],
                 &g_proj_e[((size_t)(b * Nn + k) * 3 + d) * CEQ + cl]);
        }
        cp_commit();

        u64 Sa[2], Qa[2], Da[6], Sb[2], Qb[2], Db[6];
#pragma unroll
        for (int j = 0; j < 2; j++) { Sa[j] = Qa[j] = Sb[j] = Qb[j] = 0ull; }
#pragma unroll
        for (int r = 0; r < 6; r++) { Da[r] = 0ull; Db[r] = 0ull; }

        const float* emq0 = em + (size_t)(b * Nn + q0) * (Nn * CEQ);
        const float* emq1 = emq0 + Nn * CEQ;
        const float* mq0 = sm.e.mask + (wid * 2) * 256;
        const float* mq1 = mq0 + 256;

        int buf = 0;
#pragma unroll 1
        for (int ti = 0; ti < Nn / KTE; ti++) {
            if (ti + 1 < Nn / KTE) {
                const int kb2 = (ti + 1) * KTE;
#pragma unroll
                for (int r = 0; r < 6; r++) {
                    const int j = t + r * 128;
                    const int k = j / 48, rem = j % 48;
                    const int d = rem >> 4, cl = (rem & 15) * 4;
                    cp16(&sm.e.proj[(buf ^ 1) * 3072 + k * 192 + d * 64 + cl],
                         &g_proj_e[((size_t)(b * Nn + kb2 + k) * 3 + d) * CEQ + cl]);
                }
                cp_commit();
                cp_wait<1>();
            } else {
                cp_wait<0>();
            }
            __syncthreads();
            const float* ps = sm.e.proj + buf * 3072;
            const int kb = ti * KTE;
#pragma unroll
            for (int it = 0; it < KTE / 2; it++) {
                const int kl = it * 2 + ksub;
                const int k = kb + kl;
                const float4 x0 = *(const float4*)&emq0[(size_t)k * CEQ + c4 * 4];
                const float4 x1 = *(const float4*)&emq1[(size_t)k * CEQ + c4 * 4];
                const float mk0 = mq0[k], mk1 = mq1[k];
                const float a0 = ex2f(fmaf(x0.x, L2E, mk0));
                const float a1 = ex2f(fmaf(x0.y, L2E, mk0));
                const float a2 = ex2f(fmaf(x0.z, L2E, mk0));
                const float a3 = ex2f(fmaf(x0.w, L2E, mk0));
                const float b0 = ex2f(fmaf(x1.x, L2E, mk1));
                const float b1 = ex2f(fmaf(x1.y, L2E, mk1));
                const float b2 = ex2f(fmaf(x1.z, L2E, mk1));
                const float b3 = ex2f(fmaf(x1.w, L2E, mk1));
                const u64 pA0 = pack2(a0, a1), pB0 = pack2(a2, a3);
                const u64 pA1 = pack2(b0, b1), pB1 = pack2(b2, b3);
                add2(Sa[0], pA0);      add2(Sa[1], pB0);
                add2(Sb[0], pA1);      add2(Sb[1], pB1);
                fma2(Qa[0], pA0, pA0); fma2(Qa[1], pB0, pB0);
                fma2(Qb[0], pA1, pA1); fma2(Qb[1], pB1, pB1);
                const ulonglong2 va = *(const ulonglong2*)&ps[kl * 192 +   0 + c4 * 4];
                const ulonglong2 vb = *(const ulonglong2*)&ps[kl * 192 +  64 + c4 * 4];
                const ulonglong2 vc = *(const ulonglong2*)&ps[kl * 192 + 128 + c4 * 4];
                fma2(Da[0], pA0, va.x); fma2(Da[1], pB0, va.y);
                fma2(Da[2], pA0, vb.x); fma2(Da[3], pB0, vb.y);
                fma2(Da[4], pA0, vc.x); fma2(Da[5], pB0, vc.y);
                fma2(Db[0], pA1, va.x); fma2(Db[1], pB1, va.y);
                fma2(Db[2], pA1, vb.x); fma2(Db[3], pB1, vb.y);
                fma2(Db[4], pA1, vc.x); fma2(Db[5], pB1, vc.y);
            }
            __syncthreads();
            buf ^= 1;
        }

        // reduce across the 2 ksub lanes
        {
            const int m = 16;
#pragma unroll
            for (int j = 0; j < 2; j++) {
                u64 v;
                v = __shfl_xor_sync(0xffffffffu, Sa[j], m); add2(Sa[j], v);
                v = __shfl_xor_sync(0xffffffffu, Qa[j], m); add2(Qa[j], v);
                v = __shfl_xor_sync(0xffffffffu, Sb[j], m); add2(Sb[j], v);
                v = __shfl_xor_sync(0xffffffffu, Qb[j], m); add2(Qb[j], v);
            }
#pragma unroll
            for (int r = 0; r < 6; r++) {
                u64 v;
                v = __shfl_xor_sync(0xffffffffu, Da[r], m); add2(Da[r], v);
                v = __shfl_xor_sync(0xffffffffu, Db[r], m); add2(Db[r], v);
            }
        }

        // scaled rows -> smem (overlay tile buffer 0, rows [24][68])
        if (ksub == 0) {
#pragma unroll
            for (int qq = 0; qq < 2; qq++) {
                const u64* S2 = qq ? Sb : Sa;
                const u64* Q2 = qq ? Qb : Qa;
                const u64* D2 = qq ? Db : Da;
                const float2 sA = unpack2(S2[0]), sB = unpack2(S2[1]);
                const float2 qA = unpack2(Q2[0]), qB = unpack2(Q2[1]);
                const float Sv[4] = {sA.x, sA.y, sB.x, sB.y};
                const float Qv[4] = {qA.x, qA.y, qB.x, qB.y};
                float sc[4];
#pragma unroll
                for (int j = 0; j < 4; j++) {
                    const float iv = 1.0f / Sv[j];
                    sc[j] = sqrtf(Qv[j]) * iv * iv;
                }
#pragma unroll
                for (int d = 0; d < 3; d++) {
                    const float2 dA = unpack2(D2[d * 2]), dB = unpack2(D2[d * 2 + 1]);
                    float4 o;
                    o.x = dA.x * sc[0]; o.y = dA.y * sc[1];
                    o.z = dB.x * sc[2]; o.w = dB.y * sc[3];
                    *(float4*)&sm.e.proj[((wid * 2 + qq) * 3 + d) * 68 + c4 * 4] = o;
                }
            }
        }
        __syncthreads();

        // load W_eo transposed into smem at offset 1664: Wt[c][o], stride 68
        float* Wt = sm.e.proj + 1664;
#pragma unroll
        for (int r = 0; r < 8; r++) {
            const int j = t + r * 128;        // 1024 float4
            const int o = j >> 4, cq = (j & 15) * 4;
            const float4 w = *(const float4*)&W_eo[o * 64 + cq];
            Wt[(cq + 0) * 68 + o] = w.x;
            Wt[(cq + 1) * 68 + o] = w.y;
            Wt[(cq + 2) * 68 + o] = w.z;
            Wt[(cq + 3) * 68 + o] = w.w;
        }
        __syncthreads();

        // in-CTA output projection: out[r][o] = rows[r] . W_eo[o] + b_eo[o]
        // warp handles rows [wid*6, wid*6+6); lane covers outputs o = lane*2, +1
        const u64 bias2 = *(const u64*)&b_eo[lane * 2];
#pragma unroll
        for (int rr = 0; rr < 6; rr++) {
            const int r = wid * 6 + rr;
            const int ql = r / 3, d = r - ql * 3;
            u64 acc = 0ull;
#pragma unroll
            for (int cq = 0; cq < 16; cq++) {
                const float4 rv = *(const float4*)&sm.e.proj[r * 68 + cq * 4];
                fma2(acc, pack2(rv.x, rv.x), *(const u64*)&Wt[(cq * 4 + 0) * 68 + lane * 2]);
                fma2(acc, pack2(rv.y, rv.y), *(const u64*)&Wt[(cq * 4 + 1) * 68 + lane * 2]);
                fma2(acc, pack2(rv.z, rv.z), *(const u64*)&Wt[(cq * 4 + 2) * 68 + lane * 2]);
                fma2(acc, pack2(rv.w, rv.w), *(const u64*)&Wt[(cq * 4 + 3) * 68 + lane * 2]);
            }
            add2(acc, bias2);
            const float2 ov = unpack2(acc);
            float* op = out_equi + (((size_t)(b * Nn + qg * 8 + ql) * 3 + d) * CEQ);
            *(float2*)&op[lane * 2] = ov;
        }
    } else {
        // ================= INV =================
        const int id = bx - 256;
        const int hg = id & 1, qg = (id >> 1) & 31, b = id >> 6;
        const int h = lane & 7;
        const int ksub = lane >> 3;
        const int hbase = hg * 8;
        const int q0 = qg * 8 + wid * 2;

#pragma unroll
        for (int j = 0; j < 2; j++) {
            const int* arow = adj + (size_t)(b * Nn + q0 + j) * Nn;
            const int4 a0 = *(const int4*)&arow[lane * 8];
            const int4 a1 = *(const int4*)&arow[lane * 8 + 4];
            const bool c0 = a0.x != 0, c1 = a0.y != 0, c2 = a0.z != 0, c3 = a0.w != 0;
            const bool c5 = a1.x != 0, c6 = a1.y != 0, c7 = a1.z != 0, c8 = a1.w != 0;
            const unsigned any = __ballot_sync(0xffffffffu,
                c0 | c1 | c2 | c3 | c5 | c6 | c7 | c8);
            const float neg = any ? -1e30f : 0.0f;
            float4 m0, m1;
            m0.x = c0 ? 0.0f : neg; m0.y = c1 ? 0.0f : neg;
            m0.z = c2 ? 0.0f : neg; m0.w = c3 ? 0.0f : neg;
            m1.x = c5 ? 0.0f : neg; m1.y = c6 ? 0.0f : neg;
            m1.z = c7 ? 0.0f : neg; m1.w = c8 ? 0.0f : neg;
            *(float4*)&sm.i.mask[(wid * 2 + j) * 256 + lane * 8] = m0;
            *(float4*)&sm.i.mask[(wid * 2 + j) * 256 + lane * 8 + 4] = m1;
        }
        // prefetch tile 0: KTI*8h*16e = 2048 floats = 512 float4
#pragma unroll
        for (int r = 0; r < 4; r++) {
            const int j = t + r * 128;
            const int k = j >> 5, rem = j & 31;
            const int hh = rem >> 2, e4 = (rem & 3) * 4;
            cp16(&sm.i.hf[0][hh * 260 + k * 16 + e4],
                 &g_proj_i[(size_t)(b * Nn + k) * DIN + (hbase + hh) * 16 + e4]);
        }
        cp_commit();

        float S0 = 0.0f, SQ0 = 0.0f, S1 = 0.0f, SQ1 = 0.0f;
        u64 Aa[8], Ab[8];
#pragma unroll
        for (int e = 0; e < 8; e++) { Aa[e] = 0ull; Ab[e] = 0ull; }

        const float* imq0 = im + (size_t)(b * Nn + q0) * (Nn * 16) + hbase + h;
        const float* imq1 = imq0 + Nn * 16;
        const float* mq0 = sm.i.mask + (wid * 2) * 256;
        const float* mq1 = mq0 + 256;

        int buf = 0;
#pragma unroll 1
        for (int ti = 0; ti < Nn / KTI; ti++) {
            if (ti + 1 < Nn / KTI) {
                const int kb2 = (ti + 1) * KTI;
#pragma unroll
                for (int r = 0; r < 4; r++) {
                    const int j = t + r * 128;
                    const int k = j >> 5, rem = j & 31;
                    const int hh = rem >> 2, e4 = (rem & 3) * 4;
                    cp16(&sm.i.hf[buf ^ 1][hh * 260 + k * 16 + e4],
                         &g_proj_i[(size_t)(b * Nn + kb2 + k) * DIN + (hbase + hh) * 16 + e4]);
                }
                cp_commit();
                cp_wait<1>();
            } else {
                cp_wait<0>();
            }
            __syncthreads();
            const float* hs = sm.i.hf[buf];
            const int kb = ti * KTI;
#pragma unroll
            for (int it = 0; it < KTI / 4; it++) {
                const int kl = it * 4 + ksub;
                const int k = kb + kl;
                const float x0 = imq0[(size_t)k * 16];
                const float x1 = imq1[(size_t)k * 16];
                const float p0 = ex2f(fmaf(x0, L2E, mq0[k]));
                const float p1 = ex2f(fmaf(x1, L2E, mq1[k]));
                S0 += p0; SQ0 = fmaf(p0, p0, SQ0);
                S1 += p1; SQ1 = fmaf(p1, p1, SQ1);
                const u64 pp0 = pack2(p0, p0);
                const u64 pp1 = pack2(p1, p1);
                const float* hk = hs + h * 260 + kl * 16;
                const ulonglong2 v0 = *(const ulonglong2*)&hk[0];
                const ulonglong2 v1 = *(const ulonglong2*)&hk[4];
                const ulonglong2 v2 = *(const ulonglong2*)&hk[8];
                const ulonglong2 v3 = *(const ulonglong2*)&hk[12];
                fma2(Aa[0], pp0, v0.x); fma2(Aa[1], pp0, v0.y);
                fma2(Aa[2], pp0, v1.x); fma2(Aa[3], pp0, v1.y);
                fma2(Aa[4], pp0, v2.x); fma2(Aa[5], pp0, v2.y);
                fma2(Aa[6], pp0, v3.x); fma2(Aa[7], pp0, v3.y);
                fma2(Ab[0], pp1, v0.x); fma2(Ab[1], pp1, v0.y);
                fma2(Ab[2], pp1, v1.x); fma2(Ab[3], pp1, v1.y);
                fma2(Ab[4], pp1, v2.x); fma2(Ab[5], pp1, v2.y);
                fma2(Ab[6], pp1, v3.x); fma2(Ab[7], pp1, v3.y);
            }
            __syncthreads();
            buf ^= 1;
        }

#pragma unroll
        for (int m = 8; m <= 16; m <<= 1) {
            S0  += __shfl_xor_sync(0xffffffffu, S0,  m);
            SQ0 += __shfl_xor_sync(0xffffffffu, SQ0, m);
            S1  += __shfl_xor_sync(0xffffffffu, S1,  m);
            SQ1 += __shfl_xor_sync(0xffffffffu, SQ1, m);
#pragma unroll
            for (int e = 0; e < 8; e++) {
                u64 v;
                v = __shfl_xor_sync(0xffffffffu, Aa[e], m); add2(Aa[e], v);
                v = __shfl_xor_sync(0xffffffffu, Ab[e], m); add2(Ab[e], v);
            }
        }

        if (ksub == 0) {
            const float i0 = 1.0f / S0, i1 = 1.0f / S1;
            const float sc0 = sqrtf(SQ0) * i0 * i0;
            const float sc1 = sqrtf(SQ1) * i1 * i1;
            float* o0 = g_out_i + (size_t)(b * Nn + q0) * DIN + (hbase + h) * 16;
            float* o1 = o0 + DIN;
#pragma unroll
            for (int e4 = 0; e4 < 4; e4++) {
                const float2 lo0 = unpack2(Aa[e4 * 2]);
                const float2 hi0 = unpack2(Aa[e4 * 2 + 1]);
                const float2 lo1 = unpack2(Ab[e4 * 2]);
                const float2 hi1 = unpack2(Ab[e4 * 2 + 1]);
                float4 v0, v1;
                v0.x = lo0.x * sc0; v0.y = lo0.y * sc0;
                v0.z = hi0.x * sc0; v0.w = hi0.y * sc0;
                v1.x = lo1.x * sc1; v1.y = lo1.y * sc1;
                v1.z = hi1.x * sc1; v1.w = hi1.y * sc1;
                *(float4*)&o0[e4 * 4] = v0;
                *(float4*)&o1[e4 * 4] = v1;
            }
        }
    }
}

// ---------------------------------------------------------------------------
// Output kernel (inv only): 128 CTAs, 32 m-tiles x 4 n-tiles
// ---------------------------------------------------------------------------
__global__ void __launch_bounds__(256) out_kernel(
    const float* __restrict__ W_out, const float* __restrict__ b_out,
    float* __restrict__ out)
{
    __shared__ __align__(16) float sm[2 * 2 * 16 * 68];
    const int id = blockIdx.x;
    gemm_tile64(g_out_i, W_out, b_out, out + (size_t)Bsz * Nn * 3 * CEQ,
                DIN, DIN, (id >> 2) * 64, (id & 3) * 64, sm);
}

// ---------------------------------------------------------------------------
// Launch: 3 kernels
// ---------------------------------------------------------------------------
extern "C" void kernel_launch(void* const* d_in, const int* in_sizes, int n_in,
                              void* d_out, int out_size) {
    const float* v_equi     = (const float*)d_in[0];
    const float* v_inv      = (const float*)d_in[1];
    const float* em         = (const float*)d_in[2];
    const float* im         = (const float*)d_in[3];
    const int*   adj        = (const int*)  d_in[4];
    const float* W_coord    = (const float*)d_in[5];
    const float* W_equi_out = (const float*)d_in[6];
    const float* b_equi_out = (const float*)d_in[7];
    const float* W_in       = (const float*)d_in[8];
    const float* b_in       = (const float*)d_in[9];
    const float* W_out      = (const float*)d_in[10];
    const float* b_out      = (const float*)d_in[11];
    float* out = (float*)d_out;

    prep_kernel<<<224, 256>>>(v_equi, v_inv, W_coord, W_in, b_in);
    attn_kernel<<<768, 128>>>(em, im, adj, W_equi_out, b_equi_out, out);
    out_kernel<<<128, 256>>>(W_out, b_out, out);
}

// round 13
// speedup vs baseline: 1.7214x; 1.0701x over previous
#include <cuda_runtime.h>
#include <cuda_bf16.h>
#include <cstdint>

// ---------------------------------------------------------------------------
// SemlaLayer: equi + inv attention, B=8, N=256, D_EQUI=64, H=16, D_HEAD=16
// Two-stream overlap: [null] prep_e -> equi_attn(fused out-proj)
//                     [s2]   prep_i -> inv_attn -> out_inv
// ---------------------------------------------------------------------------
#define Bsz 8
#define Nn  256
#define CEQ 64
#define DIN 256
#define L2E 1.4426950408889634f
#define KTE 16
#define KTI 16

typedef unsigned long long u64;

// Scratch (device globals; no allocation allowed)
__device__ __align__(128) float g_proj_e[Bsz * Nn * 3 * CEQ];
__device__ __align__(128) float g_proj_i[Bsz * Nn * DIN];
__device__ __align__(128) float g_out_i [Bsz * Nn * DIN];

__device__ __forceinline__ float ex2f(float x) {
    float r;
    asm("ex2.approx.ftz.f32 %0, %1;" : "=f"(r) : "f"(x));
    return r;
}
__device__ __forceinline__ u64 pack2(float lo, float hi) {
    u64 r;
    asm("mov.b64 %0, {%1, %2};" : "=l"(r) : "f"(lo), "f"(hi));
    return r;
}
__device__ __forceinline__ float2 unpack2(u64 v) {
    float2 f;
    asm("mov.b64 {%0, %1}, %2;" : "=f"(f.x), "=f"(f.y) : "l"(v));
    return f;
}
__device__ __forceinline__ void fma2(u64& d, u64 a, u64 b) {
    asm("fma.rn.f32x2 %0, %1, %2, %3;" : "=l"(d) : "l"(a), "l"(b), "l"(d));
}
__device__ __forceinline__ void add2(u64& d, u64 a) {
    asm("add.rn.f32x2 %0, %1, %2;" : "=l"(d) : "l"(a), "l"(d));
}

__device__ __forceinline__ void cp16(float* dst_smem, const float* src) {
    uint32_t d = (uint32_t)__cvta_generic_to_shared(dst_smem);
    asm volatile("cp.async.cg.shared.global [%0], [%1], 16;" :: "r"(d), "l"(src) : "memory");
}
__device__ __forceinline__ void cp_commit() {
    asm volatile("cp.async.commit_group;" ::: "memory");
}
template <int N> __device__ __forceinline__ void cp_wait() {
    asm volatile("cp.async.wait_group %0;" :: "n"(N) : "memory");
}

// ---------------------------------------------------------------------------
// f32x2 GEMM tile: C[m_base:+64, n_base:+64] = X @ W^T (+bias)
// 256 threads, BK=16, double-buffered smem, packed row-pair accumulators.
// ---------------------------------------------------------------------------
__device__ __forceinline__ void gemm_tile64(
    const float* __restrict__ X, const float* __restrict__ W,
    const float* __restrict__ bias, float* __restrict__ C,
    int Nout, int K, int m_base, int n_base, float* sm)
{
    const int t = threadIdx.x;
    const int tx = t & 15, ty = t >> 4;
    const int lm = t >> 2;
    const int lk = (t & 3) * 4;

    u64 acc[2][4];
#pragma unroll
    for (int i = 0; i < 2; i++)
#pragma unroll
        for (int j = 0; j < 4; j++) acc[i][j] = 0ull;

    {
        float4 vx = *(const float4*)&X[(size_t)(m_base + lm) * K + lk];
        float4 vw = *(const float4*)&W[(size_t)(n_base + lm) * K + lk];
        float* Xs = sm;
        float* Ws = sm + 1088;
        Xs[(lk + 0) * 68 + lm] = vx.x; Xs[(lk + 1) * 68 + lm] = vx.y;
        Xs[(lk + 2) * 68 + lm] = vx.z; Xs[(lk + 3) * 68 + lm] = vx.w;
        Ws[(lk + 0) * 68 + lm] = vw.x; Ws[(lk + 1) * 68 + lm] = vw.y;
        Ws[(lk + 2) * 68 + lm] = vw.z; Ws[(lk + 3) * 68 + lm] = vw.w;
    }
    __syncthreads();

    const int nsteps = K / 16;
    for (int s = 0; s < nsteps; s++) {
        float4 nx, nw;
        const bool more = (s + 1 < nsteps);
        if (more) {
            nx = *(const float4*)&X[(size_t)(m_base + lm) * K + (s + 1) * 16 + lk];
            nw = *(const float4*)&W[(size_t)(n_base + lm) * K + (s + 1) * 16 + lk];
        }
        const float* Xs = sm + (s & 1) * 2176;
        const float* Ws = Xs + 1088;
#pragma unroll
        for (int kk = 0; kk < 16; kk++) {
            const ulonglong2 ax = *(const ulonglong2*)&Xs[kk * 68 + ty * 4];
            const float4 bv = *(const float4*)&Ws[kk * 68 + tx * 4];
            const u64 b0 = pack2(bv.x, bv.x), b1 = pack2(bv.y, bv.y);
            const u64 b2 = pack2(bv.z, bv.z), b3 = pack2(bv.w, bv.w);
            fma2(acc[0][0], ax.x, b0); fma2(acc[0][1], ax.x, b1);
            fma2(acc[0][2], ax.x, b2); fma2(acc[0][3], ax.x, b3);
            fma2(acc[1][0], ax.y, b0); fma2(acc[1][1], ax.y, b1);
            fma2(acc[1][2], ax.y, b2); fma2(acc[1][3], ax.y, b3);
        }
        if (more) {
            float* Xd = sm + ((s + 1) & 1) * 2176;
            float* Wd = Xd + 1088;
            Xd[(lk + 0) * 68 + lm] = nx.x; Xd[(lk + 1) * 68 + lm] = nx.y;
            Xd[(lk + 2) * 68 + lm] = nx.z; Xd[(lk + 3) * 68 + lm] = nx.w;
            Wd[(lk + 0) * 68 + lm] = nw.x; Wd[(lk + 1) * 68 + lm] = nw.y;
            Wd[(lk + 2) * 68 + lm] = nw.z; Wd[(lk + 3) * 68 + lm] = nw.w;
        }
        __syncthreads();
    }

    float4 bvec;
    if (bias) bvec = *(const float4*)&bias[n_base + tx * 4];
    else      bvec = make_float4(0.f, 0.f, 0.f, 0.f);
#pragma unroll
    for (int p = 0; p < 2; p++) {
        float4 lo, hi;
        float2 f;
        f = unpack2(acc[p][0]); lo.x = f.x + bvec.x; hi.x = f.y + bvec.x;
        f = unpack2(acc[p][1]); lo.y = f.x + bvec.y; hi.y = f.y + bvec.y;
        f = unpack2(acc[p][2]); lo.z = f.x + bvec.z; hi.z = f.y + bvec.z;
        f = unpack2(acc[p][3]); lo.w = f.x + bvec.w; hi.w = f.y + bvec.w;
        const int m = m_base + ty * 4 + p * 2;
        *(float4*)&C[(size_t)m * Nout + n_base + tx * 4] = lo;
        *(float4*)&C[(size_t)(m + 1) * Nout + n_base + tx * 4] = hi;
    }
}

// ---------------------------------------------------------------------------
// prep_e: equi input GEMM (96 CTAs).   prep_i: inv input GEMM (128 CTAs).
// ---------------------------------------------------------------------------
__global__ void __launch_bounds__(256) prep_e_kernel(
    const float* __restrict__ v_equi, const float* __restrict__ W_coord)
{
    __shared__ __align__(16) float sm[2 * 2 * 16 * 68];
    gemm_tile64(v_equi, W_coord, nullptr, g_proj_e, CEQ, CEQ, blockIdx.x * 64, 0, sm);
}

__global__ void __launch_bounds__(256) prep_i_kernel(
    const float* __restrict__ v_inv,
    const float* __restrict__ W_in, const float* __restrict__ b_in)
{
    __shared__ __align__(16) float sm[2 * 2 * 16 * 68];
    const int id = blockIdx.x;                  // 32 m-tiles x 4 n-tiles
    gemm_tile64(v_inv, W_in, b_in, g_proj_i, DIN, DIN, (id >> 2) * 64, (id & 3) * 64, sm);
}

// ---------------------------------------------------------------------------
// Equi attention, 512 CTAs x 128 threads. Warp owns ONE q (4 q / CTA),
// full 64 channels; lane: c4 = lane&15, ksub = lane>>4. Fused output
// projection writes d_out directly. smem 28.7 KB -> ~7 CTAs/SM.
// ---------------------------------------------------------------------------
struct __align__(16) EquiSm {
    float proj[2 * KTE * 192];   // tile buffers; tail overlays rows + Wt here
    float mask[4 * 256];
};

__global__ void __launch_bounds__(128, 6) equi_attn_kernel(
    const float* __restrict__ em,      // [B,N,N,64]
    const int*   __restrict__ adj,     // [B,N,N]
    const float* __restrict__ W_eo,    // [64,64]
    const float* __restrict__ b_eo,    // [64]
    float* __restrict__ out_equi)      // d_out equi part [B,N,3,64]
{
    __shared__ EquiSm sm;
    const int bx = blockIdx.x;
    const int t = threadIdx.x;
    const int wid = t >> 5, lane = t & 31;
    const int c4 = lane & 15;
    const int ksub = lane >> 4;
    const int qg = bx & 63, b = bx >> 6;
    const int q = qg * 4 + wid;

    // mask from adj: warp computes its q-row
    {
        const int* arow = adj + (size_t)(b * Nn + q) * Nn;
        const int4 a0 = *(const int4*)&arow[lane * 8];
        const int4 a1 = *(const int4*)&arow[lane * 8 + 4];
        const bool c0 = a0.x != 0, c1 = a0.y != 0, c2 = a0.z != 0, c3 = a0.w != 0;
        const bool c5 = a1.x != 0, c6 = a1.y != 0, c7 = a1.z != 0, c8 = a1.w != 0;
        const unsigned any = __ballot_sync(0xffffffffu,
            c0 | c1 | c2 | c3 | c5 | c6 | c7 | c8);
        const float neg = any ? -1e30f : 0.0f;
        float4 m0, m1;
        m0.x = c0 ? 0.0f : neg; m0.y = c1 ? 0.0f : neg;
        m0.z = c2 ? 0.0f : neg; m0.w = c3 ? 0.0f : neg;
        m1.x = c5 ? 0.0f : neg; m1.y = c6 ? 0.0f : neg;
        m1.z = c7 ? 0.0f : neg; m1.w = c8 ? 0.0f : neg;
        *(float4*)&sm.mask[wid * 256 + lane * 8] = m0;
        *(float4*)&sm.mask[wid * 256 + lane * 8 + 4] = m1;
    }
    // prefetch tile 0: KTE*3*64 = 3072 floats = 768 float4, 6 per thread
#pragma unroll
    for (int r = 0; r < 6; r++) {
        const int j = t + r * 128;
        const int k = j / 48, rem = j % 48;
        const int d = rem >> 4, cl = (rem & 15) * 4;
        cp16(&sm.proj[k * 192 + d * 64 + cl],
             &g_proj_e[((size_t)(b * Nn + k) * 3 + d) * CEQ + cl]);
    }
    cp_commit();

    u64 S2[2], Q2[2], D2[6];
#pragma unroll
    for (int j = 0; j < 2; j++) { S2[j] = 0ull; Q2[j] = 0ull; }
#pragma unroll
    for (int r = 0; r < 6; r++) D2[r] = 0ull;

    const float* emq = em + (size_t)(b * Nn + q) * (Nn * CEQ);
    const float* mq = sm.mask + wid * 256;

    int buf = 0;
#pragma unroll 1
    for (int ti = 0; ti < Nn / KTE; ti++) {
        if (ti + 1 < Nn / KTE) {
            const int kb2 = (ti + 1) * KTE;
#pragma unroll
            for (int r = 0; r < 6; r++) {
                const int j = t + r * 128;
                const int k = j / 48, rem = j % 48;
                const int d = rem >> 4, cl = (rem & 15) * 4;
                cp16(&sm.proj[(buf ^ 1) * 3072 + k * 192 + d * 64 + cl],
                     &g_proj_e[((size_t)(b * Nn + kb2 + k) * 3 + d) * CEQ + cl]);
            }
            cp_commit();
            cp_wait<1>();
        } else {
            cp_wait<0>();
        }
        __syncthreads();
        const float* ps = sm.proj + buf * 3072;
        const int kb = ti * KTE;
#pragma unroll
        for (int it = 0; it < KTE / 2; it++) {
            const int kl = it * 2 + ksub;
            const int k = kb + kl;
            const float4 x = *(const float4*)&emq[(size_t)k * CEQ + c4 * 4];
            const float mk = mq[k];
            const float a0 = ex2f(fmaf(x.x, L2E, mk));
            const float a1 = ex2f(fmaf(x.y, L2E, mk));
            const float a2 = ex2f(fmaf(x.z, L2E, mk));
            const float a3 = ex2f(fmaf(x.w, L2E, mk));
            const u64 pA = pack2(a0, a1), pB = pack2(a2, a3);
            add2(S2[0], pA);      add2(S2[1], pB);
            fma2(Q2[0], pA, pA);  fma2(Q2[1], pB, pB);
            const ulonglong2 va = *(const ulonglong2*)&ps[kl * 192 +   0 + c4 * 4];
            const ulonglong2 vb = *(const ulonglong2*)&ps[kl * 192 +  64 + c4 * 4];
            const ulonglong2 vc = *(const ulonglong2*)&ps[kl * 192 + 128 + c4 * 4];
            fma2(D2[0], pA, va.x); fma2(D2[1], pB, va.y);
            fma2(D2[2], pA, vb.x); fma2(D2[3], pB, vb.y);
            fma2(D2[4], pA, vc.x); fma2(D2[5], pB, vc.y);
        }
        __syncthreads();
        buf ^= 1;
    }

    // reduce across the 2 ksub lanes
    {
#pragma unroll
        for (int j = 0; j < 2; j++) {
            u64 v;
            v = __shfl_xor_sync(0xffffffffu, S2[j], 16); add2(S2[j], v);
            v = __shfl_xor_sync(0xffffffffu, Q2[j], 16); add2(Q2[j], v);
        }
#pragma unroll
        for (int r = 0; r < 6; r++) {
            u64 v;
            v = __shfl_xor_sync(0xffffffffu, D2[r], 16); add2(D2[r], v);
        }
    }

    // scaled rows -> smem rows area [12][68] at proj[0..816)
    if (ksub == 0) {
        const float2 sA = unpack2(S2[0]), sB = unpack2(S2[1]);
        const float2 qA = unpack2(Q2[0]), qB = unpack2(Q2[1]);
        const float Sv[4] = {sA.x, sA.y, sB.x, sB.y};
        const float Qv[4] = {qA.x, qA.y, qB.x, qB.y};
        float sc[4];
#pragma unroll
        for (int j = 0; j < 4; j++) {
            const float iv = 1.0f / Sv[j];
            sc[j] = sqrtf(Qv[j]) * iv * iv;
        }
#pragma unroll
        for (int d = 0; d < 3; d++) {
            const float2 dA = unpack2(D2[d * 2]), dB = unpack2(D2[d * 2 + 1]);
            float4 o;
            o.x = dA.x * sc[0]; o.y = dA.y * sc[1];
            o.z = dB.x * sc[2]; o.w = dB.y * sc[3];
            *(float4*)&sm.proj[(wid * 3 + d) * 68 + c4 * 4] = o;
        }
    }

    // load W_eo transposed into smem at proj[1024..5376): Wt[c][o], stride 68
    float* Wt = sm.proj + 1024;
#pragma unroll
    for (int r = 0; r < 8; r++) {
        const int j = t + r * 128;        // 1024 float4
        const int o = j >> 4, cq = (j & 15) * 4;
        const float4 w = *(const float4*)&W_eo[o * 64 + cq];
        Wt[(cq + 0) * 68 + o] = w.x;
        Wt[(cq + 1) * 68 + o] = w.y;
        Wt[(cq + 2) * 68 + o] = w.z;
        Wt[(cq + 3) * 68 + o] = w.w;
    }
    __syncthreads();

    // in-CTA output projection: warp handles rows [wid*3, wid*3+3);
    // lane covers outputs o = lane*2, lane*2+1
    const u64 bias2 = *(const u64*)&b_eo[lane * 2];
#pragma unroll
    for (int d = 0; d < 3; d++) {
        const int r = wid * 3 + d;
        u64 acc = 0ull;
#pragma unroll
        for (int cq = 0; cq < 16; cq++) {
            const float4 rv = *(const float4*)&sm.proj[r * 68 + cq * 4];
            fma2(acc, pack2(rv.x, rv.x), *(const u64*)&Wt[(cq * 4 + 0) * 68 + lane * 2]);
            fma2(acc, pack2(rv.y, rv.y), *(const u64*)&Wt[(cq * 4 + 1) * 68 + lane * 2]);
            fma2(acc, pack2(rv.z, rv.z), *(const u64*)&Wt[(cq * 4 + 2) * 68 + lane * 2]);
            fma2(acc, pack2(rv.w, rv.w), *(const u64*)&Wt[(cq * 4 + 3) * 68 + lane * 2]);
        }
        add2(acc, bias2);
        const float2 ov = unpack2(acc);
        float* op = out_equi + (((size_t)(b * Nn + q) * 3 + d) * CEQ);
        *(float2*)&op[lane * 2] = ov;
    }
}

// ---------------------------------------------------------------------------
// Inv attention, 512 CTAs x 128 threads (unchanged structure from R12).
// ---------------------------------------------------------------------------
struct __align__(16) InvSm {
    float hf[2][8 * 260];
    float mask[8 * 256];
};

__global__ void __launch_bounds__(128, 4) inv_attn_kernel(
    const float* __restrict__ im,      // [B,N,N,16]
    const int*   __restrict__ adj)     // [B,N,N]
{
    __shared__ InvSm sm;
    const int id = blockIdx.x;
    const int t = threadIdx.x;
    const int wid = t >> 5, lane = t & 31;
    const int hg = id & 1, qg = (id >> 1) & 31, b = id >> 6;
    const int h = lane & 7;
    const int ksub = lane >> 3;
    const int hbase = hg * 8;
    const int q0 = qg * 8 + wid * 2;

#pragma unroll
    for (int j = 0; j < 2; j++) {
        const int* arow = adj + (size_t)(b * Nn + q0 + j) * Nn;
        const int4 a0 = *(const int4*)&arow[lane * 8];
        const int4 a1 = *(const int4*)&arow[lane * 8 + 4];
        const bool c0 = a0.x != 0, c1 = a0.y != 0, c2 = a0.z != 0, c3 = a0.w != 0;
        const bool c5 = a1.x != 0, c6 = a1.y != 0, c7 = a1.z != 0, c8 = a1.w != 0;
        const unsigned any = __ballot_sync(0xffffffffu,
            c0 | c1 | c2 | c3 | c5 | c6 | c7 | c8);
        const float neg = any ? -1e30f : 0.0f;
        float4 m0, m1;
        m0.x = c0 ? 0.0f : neg; m0.y = c1 ? 0.0f : neg;
        m0.z = c2 ? 0.0f : neg; m0.w = c3 ? 0.0f : neg;
        m1.x = c5 ? 0.0f : neg; m1.y = c6 ? 0.0f : neg;
        m1.z = c7 ? 0.0f : neg; m1.w = c8 ? 0.0f : neg;
        *(float4*)&sm.mask[(wid * 2 + j) * 256 + lane * 8] = m0;
        *(float4*)&sm.mask[(wid * 2 + j) * 256 + lane * 8 + 4] = m1;
    }
    // prefetch tile 0: KTI*8h*16e = 2048 floats = 512 float4
#pragma unroll
    for (int r = 0; r < 4; r++) {
        const int j = t + r * 128;
        const int k = j >> 5, rem = j & 31;
        const int hh = rem >> 2, e4 = (rem & 3) * 4;
        cp16(&sm.hf[0][hh * 260 + k * 16 + e4],
             &g_proj_i[(size_t)(b * Nn + k) * DIN + (hbase + hh) * 16 + e4]);
    }
    cp_commit();

    float S0 = 0.0f, SQ0 = 0.0f, S1 = 0.0f, SQ1 = 0.0f;
    u64 Aa[8], Ab[8];
#pragma unroll
    for (int e = 0; e < 8; e++) { Aa[e] = 0ull; Ab[e] = 0ull; }

    const float* imq0 = im + (size_t)(b * Nn + q0) * (Nn * 16) + hbase + h;
    const float* imq1 = imq0 + Nn * 16;
    const float* mq0 = sm.mask + (wid * 2) * 256;
    const float* mq1 = mq0 + 256;

    int buf = 0;
#pragma unroll 1
    for (int ti = 0; ti < Nn / KTI; ti++) {
        if (ti + 1 < Nn / KTI) {
            const int kb2 = (ti + 1) * KTI;
#pragma unroll
            for (int r = 0; r < 4; r++) {
                const int j = t + r * 128;
                const int k = j >> 5, rem = j & 31;
                const int hh = rem >> 2, e4 = (rem & 3) * 4;
                cp16(&sm.hf[buf ^ 1][hh * 260 + k * 16 + e4],
                     &g_proj_i[(size_t)(b * Nn + kb2 + k) * DIN + (hbase + hh) * 16 + e4]);
            }
            cp_commit();
            cp_wait<1>();
        } else {
            cp_wait<0>();
        }
        __syncthreads();
        const float* hs = sm.hf[buf];
        const int kb = ti * KTI;
#pragma unroll
        for (int it = 0; it < KTI / 4; it++) {
            const int kl = it * 4 + ksub;
            const int k = kb + kl;
            const float x0 = imq0[(size_t)k * 16];
            const float x1 = imq1[(size_t)k * 16];
            const float p0 = ex2f(fmaf(x0, L2E, mq0[k]));
            const float p1 = ex2f(fmaf(x1, L2E, mq1[k]));
            S0 += p0; SQ0 = fmaf(p0, p0, SQ0);
            S1 += p1; SQ1 = fmaf(p1, p1, SQ1);
            const u64 pp0 = pack2(p0, p0);
            const u64 pp1 = pack2(p1, p1);
            const float* hk = hs + h * 260 + kl * 16;
            const ulonglong2 v0 = *(const ulonglong2*)&hk[0];
            const ulonglong2 v1 = *(const ulonglong2*)&hk[4];
            const ulonglong2 v2 = *(const ulonglong2*)&hk[8];
            const ulonglong2 v3 = *(const ulonglong2*)&hk[12];
            fma2(Aa[0], pp0, v0.x); fma2(Aa[1], pp0, v0.y);
            fma2(Aa[2], pp0, v1.x); fma2(Aa[3], pp0, v1.y);
            fma2(Aa[4], pp0, v2.x); fma2(Aa[5], pp0, v2.y);
            fma2(Aa[6], pp0, v3.x); fma2(Aa[7], pp0, v3.y);
            fma2(Ab[0], pp1, v0.x); fma2(Ab[1], pp1, v0.y);
            fma2(Ab[2], pp1, v1.x); fma2(Ab[3], pp1, v1.y);
            fma2(Ab[4], pp1, v2.x); fma2(Ab[5], pp1, v2.y);
            fma2(Ab[6], pp1, v3.x); fma2(Ab[7], pp1, v3.y);
        }
        __syncthreads();
        buf ^= 1;
    }

#pragma unroll
    for (int m = 8; m <= 16; m <<= 1) {
        S0  += __shfl_xor_sync(0xffffffffu, S0,  m);
        SQ0 += __shfl_xor_sync(0xffffffffu, SQ0, m);
        S1  += __shfl_xor_sync(0xffffffffu, S1,  m);
        SQ1 += __shfl_xor_sync(0xffffffffu, SQ1, m);
#pragma unroll
        for (int e = 0; e < 8; e++) {
            u64 v;
            v = __shfl_xor_sync(0xffffffffu, Aa[e], m); add2(Aa[e], v);
            v = __shfl_xor_sync(0xffffffffu, Ab[e], m); add2(Ab[e], v);
        }
    }

    if (ksub == 0) {
        const float i0 = 1.0f / S0, i1 = 1.0f / S1;
        const float sc0 = sqrtf(SQ0) * i0 * i0;
        const float sc1 = sqrtf(SQ1) * i1 * i1;
        float* o0 = g_out_i + (size_t)(b * Nn + q0) * DIN + (hbase + h) * 16;
        float* o1 = o0 + DIN;
#pragma unroll
        for (int e4 = 0; e4 < 4; e4++) {
            const float2 lo0 = unpack2(Aa[e4 * 2]);
            const float2 hi0 = unpack2(Aa[e4 * 2 + 1]);
            const float2 lo1 = unpack2(Ab[e4 * 2]);
            const float2 hi1 = unpack2(Ab[e4 * 2 + 1]);
            float4 v0, v1;
            v0.x = lo0.x * sc0; v0.y = lo0.y * sc0;
            v0.z = hi0.x * sc0; v0.w = hi0.y * sc0;
            v1.x = lo1.x * sc1; v1.y = lo1.y * sc1;
            v1.z = hi1.x * sc1; v1.w = hi1.y * sc1;
            *(float4*)&o0[e4 * 4] = v0;
            *(float4*)&o1[e4 * 4] = v1;
        }
    }
}

// ---------------------------------------------------------------------------
// Output kernel (inv only): 128 CTAs, 32 m-tiles x 4 n-tiles
// ---------------------------------------------------------------------------
__global__ void __launch_bounds__(256) out_kernel(
    const float* __restrict__ W_out, const float* __restrict__ b_out,
    float* __restrict__ out)
{
    __shared__ __align__(16) float sm[2 * 2 * 16 * 68];
    const int id = blockIdx.x;
    gemm_tile64(g_out_i, W_out, b_out, out + (size_t)Bsz * Nn * 3 * CEQ,
                DIN, DIN, (id >> 2) * 64, (id & 3) * 64, sm);
}

// ---------------------------------------------------------------------------
// Launch: two-stream fork/join (graph-capturable pattern).
//   null: prep_e -> equi_attn
//   s2:   prep_i -> inv_attn -> out_inv
// ---------------------------------------------------------------------------
extern "C" void kernel_launch(void* const* d_in, const int* in_sizes, int n_in,
                              void* d_out, int out_size) {
    const float* v_equi     = (const float*)d_in[0];
    const float* v_inv      = (const float*)d_in[1];
    const float* em         = (const float*)d_in[2];
    const float* im         = (const float*)d_in[3];
    const int*   adj        = (const int*)  d_in[4];
    const float* W_coord    = (const float*)d_in[5];
    const float* W_equi_out = (const float*)d_in[6];
    const float* b_equi_out = (const float*)d_in[7];
    const float* W_in       = (const float*)d_in[8];
    const float* b_in       = (const float*)d_in[9];
    const float* W_out      = (const float*)d_in[10];
    const float* b_out      = (const float*)d_in[11];
    float* out = (float*)d_out;

    static cudaStream_t s2 = nullptr;
    static cudaEvent_t ev_fork = nullptr, ev_join = nullptr;
    if (s2 == nullptr) {
        cudaStreamCreateWithFlags(&s2, cudaStreamNonBlocking);
        cudaEventCreateWithFlags(&ev_fork, cudaEventDisableTiming);
        cudaEventCreateWithFlags(&ev_join, cudaEventDisableTiming);
    }

    // fork: s2 branches off the (capture) null stream
    cudaEventRecord(ev_fork, 0);
    cudaStreamWaitEvent(s2, ev_fork, 0);

    // stream B: inv chain
    prep_i_kernel<<<128, 256, 0, s2>>>(v_inv, W_in, b_in);
    inv_attn_kernel<<<512, 128, 0, s2>>>(im, adj);
    out_kernel<<<128, 256, 0, s2>>>(W_out, b_out, out);
    cudaEventRecord(ev_join, s2);

    // stream A (null): equi chain
    prep_e_kernel<<<96, 256>>>(v_equi, W_coord);
    equi_attn_kernel<<<512, 128>>>(em, adj, W_equi_out, b_equi_out, out);

    // join
    cudaStreamWaitEvent(0, ev_join, 0);
}